// round 1
// baseline (speedup 1.0000x reference)
#include <cuda_runtime.h>
#include <math.h>

#define NBATCH 2048
#define ALPHA 1e-4f
#define LN_EPS 1e-5f

#define XR_ELEMS (NBATCH*62*64)      /* 8126464 */
#define S_BASE   (XR_ELEMS + 2)

__global__ void zero_loss_kernel(float* out) {
    if (threadIdx.x < 2) out[XR_ELEMS + threadIdx.x] = 0.0f;
}

__device__ __forceinline__ float sigmoidf(float x){ return 1.0f/(1.0f+expf(-x)); }

__global__ void __launch_bounds__(256,1) stgcn_kernel(
    const float* __restrict__ gx, const float* __restrict__ gU1,
    const float* __restrict__ gU2, const float* __restrict__ gU3,
    const float* __restrict__ gbe, const float* __restrict__ gVe,
    const float* __restrict__ gW1, const float* __restrict__ gW2,
    const float* __restrict__ gW3, const float* __restrict__ gbs,
    const float* __restrict__ gVs, const float* __restrict__ ga,
    const float* __restrict__ gTheta, const float* __restrict__ gtw,
    const float* __restrict__ gtb, const float* __restrict__ grw,
    const float* __restrict__ grb, const float* __restrict__ ggamma,
    const float* __restrict__ gbeta, float* __restrict__ out)
{
    extern __shared__ float smarr[];
    const int tid = threadIdx.x;
    const int b = blockIdx.x;

    float* sx    = smarr;              // 932  : x[b]  [t][v][f] (930 used)
    float* sxT   = sx   + 932;         // 932  : x_TAt [t][v][f]
    float* bufS  = sxT  + 932;         // 3844 : tmpS -> S [i][j]
    float* bufAt = bufS + 3844;        // 3844 : Sm -> spatial_At [u][v]
    float* bufSg = bufAt+ 3844;        // 3968 : sigmoid(s_prod+bs) [w][v] rowstride 64
    float* Vs_s  = bufSg+ 3968;        // 3844
    float* tw_s  = Vs_s + 3844;        // 12288 [o2][c][t]
    float* Th_s  = tw_s + 12288;       // 960  [k][f][o]
    float* sg    = Th_s + 960;         // 12288 spatial_gcn [t][c][v] rowstride 64
    float* zb    = sg   + 12288;       // 4032 z [v][o] rowstride 65
    float* U1_s  = zb   + 4032;        // 64
    float* U2_s  = U1_s + 64;          // 312
    float* U3_s  = U2_s + 312;         // 8
    float* be_s  = U3_s + 8;           // 12
    float* Ve_s  = be_s + 12;          // 12
    float* W1_s  = Ve_s + 12;          // 4
    float* W2_s  = W1_s + 4;           // 16
    float* W3_s  = W2_s + 16;          // 8
    float* a_s   = W3_s + 8;           // 8
    float* tb_s  = a_s  + 8;           // 64
    float* rw_s  = tb_s + 64;          // 320
    float* rb_s  = rw_s + 320;         // 64
    float* gam_s = rb_s + 64;          // 64
    float* bet_s = gam_s+ 64;          // 64
    float* y_s   = bet_s+ 64;          // 16
    float* lhs_s = y_s  + 16;          // 188 [t][u]
    float* rhs_s = lhs_s+ 188;         // 188 [v][t]
    float* prod_s= rhs_s+ 188;         // 12
    float* E_s   = prod_s+12;          // 12
    float* At_s  = E_s  + 12;          // 12  [t][u]
    float* slhs_s= At_s + 12;          // 188 [v][s]
    float* srhs_s= slhs_s+188;         // 188 [t][v]
    float* colsum= srhs_s+188;         // 64
    float* DgS_s = colsum+ 64;         // 64
    float* d2s_s = DgS_s + 64;         // 64
    float* mu_s  = d2s_s + 64;         // 64
    float* iv_s  = mu_s  + 64;         // 64
    float* red_s = iv_s  + 64;         // 256

    // ---------------- Phase 0: stage inputs ----------------
    for (int i = tid; i < 930;   i += 256) sx[i]   = gx[(size_t)b*930 + i];
    for (int i = tid; i < 3844;  i += 256) Vs_s[i] = gVs[i];
    for (int i = tid; i < 12288; i += 256) tw_s[i] = gtw[i];
    for (int i = tid; i < 960;   i += 256) Th_s[i] = gTheta[i];
    for (int i = tid; i < 310;   i += 256) U2_s[i] = gU2[i];
    for (int i = tid; i < 320;   i += 256) rw_s[i] = grw[i];
    if (tid < 62) U1_s[tid] = gU1[tid];
    if (tid < 5)  U3_s[tid] = gU3[tid];
    if (tid < 9)  be_s[tid] = gbe[tid];
    if (tid < 9)  Ve_s[tid] = gVe[tid];
    if (tid < 3)  W1_s[tid] = gW1[tid];
    if (tid < 15) W2_s[tid] = gW2[tid];
    if (tid < 5)  W3_s[tid] = gW3[tid];
    if (tid < 5)  a_s[tid]  = ga[tid];
    if (tid < 64) { tb_s[tid]=gtb[tid]; rb_s[tid]=grb[tid]; gam_s[tid]=ggamma[tid]; bet_s[tid]=gbeta[tid]; }
    __syncthreads();

    // ---------------- Phase 1: temporal attention ----------------
    if (tid < 15) {                    // y[t][f] = sum_v x[t][v][f]*U1[v]
        int t = tid/5, f = tid%5;
        float s = 0.f;
        for (int v = 0; v < 62; v++) s += sx[t*310+v*5+f]*U1_s[v];
        y_s[t*5+f] = s;
    }
    if (tid < 186) {                   // rhs[v][t] = sum_f U3[f]*x[t][v][f]
        int v = tid/3, t = tid%3;
        const float* xr = sx + t*310 + v*5;
        float s = 0.f;
        #pragma unroll
        for (int f=0; f<5; f++) s += U3_s[f]*xr[f];
        rhs_s[v*3+t] = s;
    }
    __syncthreads();
    if (tid < 186) {                   // lhs[t][u] = sum_f y[t][f]*U2[f][u]
        int t = tid/62, u = tid%62;
        float s = 0.f;
        #pragma unroll
        for (int f=0; f<5; f++) s += y_s[t*5+f]*U2_s[f*62+u];
        lhs_s[t*62+u] = s;
    }
    __syncthreads();
    if (tid < 9) {                     // prod[t][u] = sum_v lhs[t][v]*rhs[v][u]
        int t = tid/3, u = tid%3;
        float s = 0.f;
        for (int v=0; v<62; v++) s += lhs_s[t*62+v]*rhs_s[v*3+u];
        prod_s[t*3+u] = s;
    }
    __syncthreads();
    if (tid < 9) {                     // E[t][u] = sum_s Ve[t][s]*sig(prod[s][u]+be[s][u])
        int t = tid/3, u = tid%3;
        float s = 0.f;
        #pragma unroll
        for (int k=0; k<3; k++) s += Ve_s[t*3+k]*sigmoidf(prod_s[k*3+u]+be_s[k*3+u]);
        E_s[t*3+u] = s;
    }
    __syncthreads();
    if (tid < 3) {                     // softmax over t per column u
        int u = tid;
        float m = fmaxf(E_s[u], fmaxf(E_s[3+u], E_s[6+u]));
        float e0=expf(E_s[u]-m), e1=expf(E_s[3+u]-m), e2=expf(E_s[6+u]-m);
        float inv = 1.0f/(e0+e1+e2);
        At_s[u]=e0*inv; At_s[3+u]=e1*inv; At_s[6+u]=e2*inv;
    }
    __syncthreads();
    for (int i = tid; i < 930; i += 256) {   // x_TAt[u][v][f]
        int u = i/310, r = i%310;
        sxT[i] = (sx[r]*At_s[u] + sx[310+r]*At_s[3+u] + sx[620+r]*At_s[6+u]) * 0.056796183f;
    }
    __syncthreads();

    // ---------------- Phase 2: spatial attention ----------------
    if (tid < 186) {                   // s_lhs[v][s]
        int v = tid/3, s = tid%3;
        float acc = 0.f;
        #pragma unroll
        for (int f=0; f<5; f++) {
            float yv = sxT[v*5+f]*W1_s[0] + sxT[310+v*5+f]*W1_s[1] + sxT[620+v*5+f]*W1_s[2];
            acc += yv*W2_s[f*3+s];
        }
        slhs_s[v*3+s] = acc;
    }
    if (tid < 186) {                   // s_rhs[t][v]
        int t = tid/62, v = tid%62;
        const float* xr = sxT + t*310 + v*5;
        float s = 0.f;
        #pragma unroll
        for (int f=0; f<5; f++) s += W3_s[f]*xr[f];
        srhs_s[t*62+v] = s;
    }
    __syncthreads();
    for (int i = tid; i < 3844; i += 256) {  // sig(s_prod+bs) [w][v], rowstride 64
        int w = i/62, v = i%62;
        float p = slhs_s[w*3]*srhs_s[v] + slhs_s[w*3+1]*srhs_s[62+v]
                + slhs_s[w*3+2]*srhs_s[124+v] + gbs[i];
        bufSg[w*64+v] = sigmoidf(p);
    }
    if (tid < 62) { bufSg[tid*64+62]=0.f; bufSg[tid*64+63]=0.f; }
    __syncthreads();
    {   // Sm[u][v] = sum_w Vs[u][w]*sig[w][v] ; 1x16 register tile + float4 loads
        int u = tid>>2, vq = tid&3;
        if (u < 62) {
            float acc[16];
            #pragma unroll
            for (int k=0;k<16;k++) acc[k]=0.f;
            for (int w=0; w<62; w++) {
                float vsv = Vs_s[u*62+w];
                const float4* rowp = reinterpret_cast<const float4*>(bufSg + w*64 + vq*16);
                #pragma unroll
                for (int q=0;q<4;q++) {
                    float4 sv = rowp[q];
                    acc[q*4+0] += vsv*sv.x; acc[q*4+1] += vsv*sv.y;
                    acc[q*4+2] += vsv*sv.z; acc[q*4+3] += vsv*sv.w;
                }
            }
            #pragma unroll
            for (int k=0;k<16;k++) {
                int v = vq*16+k;
                if (v < 62) bufAt[u*62+v] = acc[k];
            }
        }
    }
    __syncthreads();
    if (tid < 62) {                    // softmax over u per column v
        int v = tid;
        float m = -1e30f;
        for (int u=0; u<62; u++) m = fmaxf(m, bufAt[u*62+v]);
        float ssum = 0.f;
        for (int u=0; u<62; u++) { float e = expf(bufAt[u*62+v]-m); bufAt[u*62+v]=e; ssum+=e; }
        float inv = 1.0f/ssum;
        for (int u=0; u<62; u++) bufAt[u*62+v] *= inv;
    }
    __syncthreads();

    // ---------------- Phase 3: S matrix + losses ----------------
    const float* xm = sx + 310;        // x[:,1]
    {
        float a0=a_s[0],a1=a_s[1],a2=a_s[2],a3=a_s[3],a4=a_s[4];
        for (int i = tid; i < 3844; i += 256) {
            int ii = i/62, jj = i%62;
            const float* xi = xm + ii*5; const float* xj = xm + jj*5;
            float e = fabsf(xi[0]-xj[0])*a0 + fabsf(xi[1]-xj[1])*a1 + fabsf(xi[2]-xj[2])*a2
                    + fabsf(xi[3]-xj[3])*a3 + fabsf(xi[4]-xj[4])*a4;
            bufS[i] = expf(fmaxf(e, 0.0f));
        }
    }
    __syncthreads();
    if (tid < 62) {
        int j = tid; float cs = 0.f;
        for (int i=0; i<62; i++) cs += bufS[i*62+j];
        colsum[j] = cs;
    }
    __syncthreads();
    for (int i = tid; i < 3844; i += 256) {
        float s = bufS[i] / colsum[i%62];
        bufS[i] = s;
        out[S_BASE + (size_t)b*3844 + i] = s;
    }
    __syncthreads();
    if (tid < 62) {                    // Dg[j] = colsum of normalized S (~1, exact)
        int j = tid; float cs = 0.f;
        for (int i=0; i<62; i++) cs += bufS[i*62+j];
        DgS_s[j] = cs;
    }
    if (tid < 62) {                    // d2row[j] = sum_{i,f} (xm[j]-xm[i])^2
        int j = tid; const float* xj = xm + j*5; float dd = 0.f;
        for (int i=0; i<62; i++) {
            const float* xi = xm + i*5;
            #pragma unroll
            for (int f=0; f<5; f++) { float d = xj[f]-xi[f]; dd += d*d; }
        }
        d2s_s[j] = dd;
    }
    {   // Sloss block partial
        float sl = 0.f;
        for (int i = tid; i < 3844; i += 256) sl += bufS[i]*bufS[i];
        red_s[tid] = sl;
    }
    __syncthreads();
    for (int s = 128; s > 0; s >>= 1) {
        if (tid < s) red_s[tid] += red_s[tid+s];
        __syncthreads();
    }
    if (tid == 0) {
        atomicAdd(out + XR_ELEMS, red_s[0] * (ALPHA/(float)NBATCH));
        float dp = 0.f;
        for (int j=0; j<62; j++) dp += DgS_s[j]*d2s_s[j];
        atomicAdd(out + XR_ELEMS + 1, dp * ALPHA);
    }

    // ---------------- Phase 4: cheb * spatial_At * x * Theta -> spatial_gcn ----------------
    if (tid < 186) {
        int t = tid/62, v = tid%62;
        float acc[15];
        #pragma unroll
        for (int k=0;k<15;k++) acc[k]=0.f;
        float dgm1 = DgS_s[v] - 1.0f;
        for (int u=0; u<62; u++) {
            float s  = bufS[u*62+v];
            float at = bufAt[u*62+v];
            float delta = (u==v) ? 1.0f : 0.0f;
            float lt = dgm1*delta - s;                 // L_t[u][v]
            float c2 = 2.0f*lt*lt - delta;             // cheb2 (elementwise!)
            float t0 = delta*at, t1 = lt*at, t2 = c2*at;
            const float* xr = sx + t*310 + u*5;
            #pragma unroll
            for (int f=0; f<5; f++) {
                float xv = xr[f];
                acc[f]    += t0*xv;
                acc[5+f]  += t1*xv;
                acc[10+f] += t2*xv;
            }
        }
        #pragma unroll 4
        for (int o=0; o<64; o++) {
            float z = 0.f;
            #pragma unroll
            for (int kf=0; kf<15; kf++) z += acc[kf]*Th_s[kf*64+o];
            sg[t*4096 + o*64 + v] = fmaxf(z, 0.0f);
        }
    }
    for (int i = tid; i < 192; i += 256) {   // zero sg pad cols 62,63
        int t = i/64, c = i%64;
        sg[t*4096 + c*64 + 62] = 0.f;
        sg[t*4096 + c*64 + 63] = 0.f;
    }
    __syncthreads();

    // ---------------- Phase 5: temporal conv + residual + relu ----------------
    {
        int o2 = tid>>2, vq = tid&3;
        float acc[16];
        #pragma unroll
        for (int k=0;k<16;k++) acc[k]=0.f;
        for (int c=0; c<64; c++) {
            const float* twp = tw_s + (o2*64+c)*3;
            #pragma unroll
            for (int t=0; t<3; t++) {
                float w = twp[t];
                const float4* rowp = reinterpret_cast<const float4*>(sg + t*4096 + c*64 + vq*16);
                #pragma unroll
                for (int q=0;q<4;q++) {
                    float4 sv = rowp[q];
                    acc[q*4+0] += w*sv.x; acc[q*4+1] += w*sv.y;
                    acc[q*4+2] += w*sv.z; acc[q*4+3] += w*sv.w;
                }
            }
        }
        float tbv = tb_s[o2], rbv = rb_s[o2];
        const float* rwp = rw_s + o2*5;
        #pragma unroll
        for (int k=0;k<16;k++) {
            int v = vq*16+k;
            if (v < 62) {
                float tcv = (acc[k] + tbv) * 0.25819889f;   // /sqrt(15)
                const float* x0 = sx + v*5;                 // x[b,0,v,:]
                float resv = rbv + x0[0]*rwp[0]+x0[1]*rwp[1]+x0[2]*rwp[2]
                                 + x0[3]*rwp[3]+x0[4]*rwp[4];
                zb[v*65+o2] = fmaxf(resv + tcv, 0.0f);
            }
        }
    }
    __syncthreads();

    // ---------------- Phase 6: LayerNorm over H2 + writeback ----------------
    if (tid < 62) {
        int v = tid;
        float s = 0.f;
        for (int o=0; o<64; o++) s += zb[v*65+o];
        float mu = s * (1.0f/64.0f);
        float vv = 0.f;
        for (int o=0; o<64; o++) { float d = zb[v*65+o]-mu; vv += d*d; }
        vv *= (1.0f/64.0f);
        mu_s[v] = mu;
        iv_s[v] = rsqrtf(vv + LN_EPS);
    }
    __syncthreads();
    for (int i = tid; i < 3968; i += 256) {
        int v = i>>6, o = i&63;
        float val = (zb[v*65+o]-mu_s[v])*iv_s[v]*gam_s[o] + bet_s[o];
        out[(size_t)b*3968 + i] = val;
    }
}

#define SMEM_BYTES (49332*4)

extern "C" void kernel_launch(void* const* d_in, const int* in_sizes, int n_in,
                              void* d_out, int out_size) {
    const float* x     = (const float*)d_in[0];
    const float* U1    = (const float*)d_in[1];
    const float* U2    = (const float*)d_in[2];
    const float* U3    = (const float*)d_in[3];
    const float* be    = (const float*)d_in[4];
    const float* Ve    = (const float*)d_in[5];
    const float* W1    = (const float*)d_in[6];
    const float* W2    = (const float*)d_in[7];
    const float* W3    = (const float*)d_in[8];
    const float* bs    = (const float*)d_in[9];
    const float* Vs    = (const float*)d_in[10];
    const float* a     = (const float*)d_in[11];
    const float* Theta = (const float*)d_in[12];
    const float* tw    = (const float*)d_in[13];
    const float* tb    = (const float*)d_in[14];
    const float* rw    = (const float*)d_in[15];
    const float* rb    = (const float*)d_in[16];
    const float* gamma = (const float*)d_in[17];
    const float* beta  = (const float*)d_in[18];
    float* out = (float*)d_out;

    cudaFuncSetAttribute(stgcn_kernel, cudaFuncAttributeMaxDynamicSharedMemorySize, SMEM_BYTES);

    zero_loss_kernel<<<1, 32>>>(out);
    stgcn_kernel<<<NBATCH, 256, SMEM_BYTES>>>(x, U1, U2, U3, be, Ve, W1, W2, W3,
                                              bs, Vs, a, Theta, tw, tb, rw, rb,
                                              gamma, beta, out);
}

// round 2
// speedup vs baseline: 1.2390x; 1.2390x over previous
#include <cuda_runtime.h>
#include <math.h>

#define NBATCH 2048
#define ALPHA 1e-4f
#define LN_EPS 1e-5f
#define NT 512

#define XR_ELEMS (NBATCH*62*64)      /* 8126464 */
#define S_BASE   (XR_ELEMS + 2)

__global__ void zero_loss_kernel(float* out) {
    if (threadIdx.x < 2) out[XR_ELEMS + threadIdx.x] = 0.0f;
}

__device__ __forceinline__ float sigmoidf(float x){ return 1.0f/(1.0f+expf(-x)); }

__global__ void __launch_bounds__(NT,1) stgcn_kernel(
    const float* __restrict__ gx, const float* __restrict__ gU1,
    const float* __restrict__ gU2, const float* __restrict__ gU3,
    const float* __restrict__ gbe, const float* __restrict__ gVe,
    const float* __restrict__ gW1, const float* __restrict__ gW2,
    const float* __restrict__ gW3, const float* __restrict__ gbs,
    const float* __restrict__ gVs, const float* __restrict__ ga,
    const float* __restrict__ gTheta, const float* __restrict__ gtw,
    const float* __restrict__ gtb, const float* __restrict__ grw,
    const float* __restrict__ grb, const float* __restrict__ ggamma,
    const float* __restrict__ gbeta, float* __restrict__ out)
{
    extern __shared__ float smarr[];
    const int tid = threadIdx.x;
    const int b = blockIdx.x;

    float* sx    = smarr;              // 932  : x[b]  [t][v][f] (930 used)
    float* sxT   = sx   + 932;         // 932  : x_TAt [t][v][f]
    float* bufS  = sxT  + 932;         // 3844 : tmpS -> S [i][j]
    float* bufAt = bufS + 3844;        // 3848 : Sm -> spatial_At [u][v] (+pad)
    float* bufSg = bufAt+ 3848;        // 3968 : sigmoid(s_prod+bs) [w][v] rowstride 64
    float* Vs_s  = bufSg+ 3968;        // 3844
    float* tw_s  = Vs_s + 3844;        // 12288 [o2][c][t]
    float* Th_s  = tw_s + 12288;       // 960  [k][f][o]
    float* sg    = Th_s + 960;         // 12288 spatial_gcn [t][c][v] rowstride 64
    float* zb    = sg   + 12288;       // 4032 z [v][o] rowstride 65
    float* U1_s  = zb   + 4032;        // 64
    float* U2_s  = U1_s + 64;          // 312
    float* U3_s  = U2_s + 312;         // 8
    float* be_s  = U3_s + 8;           // 12
    float* Ve_s  = be_s + 12;          // 12
    float* W1_s  = Ve_s + 12;          // 4
    float* W2_s  = W1_s + 4;           // 16
    float* W3_s  = W2_s + 16;          // 8
    float* a_s   = W3_s + 8;           // 8
    float* tb_s  = a_s  + 8;           // 64
    float* rw_s  = tb_s + 64;          // 320
    float* rb_s  = rw_s + 320;         // 64
    float* gam_s = rb_s + 64;          // 64
    float* bet_s = gam_s+ 64;          // 64
    float* y_s   = bet_s+ 64;          // 16
    float* lhs_s = y_s  + 16;          // 188 [t][u]
    float* rhs_s = lhs_s+ 188;         // 188 [v][t]
    float* prod_s= rhs_s+ 188;         // 12
    float* E_s   = prod_s+12;          // 12
    float* At_s  = E_s  + 12;          // 12  [t][u]
    float* slhs_s= At_s + 12;          // 188 [v][s]
    float* srhs_s= slhs_s+188;         // 188 [t][v]
    float* colsum= srhs_s+188;         // 64
    float* DgS_s = colsum+ 64;         // 64
    float* d2s_s = DgS_s + 64;         // 64
    float* mu_s  = d2s_s + 64;         // 64
    float* iv_s  = mu_s  + 64;         // 64
    float* red_s = iv_s  + 64;         // 512

    // ---------------- Phase 0: stage inputs ----------------
    for (int i = tid; i < 930;   i += NT) sx[i]   = gx[(size_t)b*930 + i];
    for (int i = tid; i < 3844;  i += NT) Vs_s[i] = gVs[i];
    for (int i = tid; i < 12288; i += NT) tw_s[i] = gtw[i];
    for (int i = tid; i < 960;   i += NT) Th_s[i] = gTheta[i];
    for (int i = tid; i < 310;   i += NT) U2_s[i] = gU2[i];
    for (int i = tid; i < 320;   i += NT) rw_s[i] = grw[i];
    if (tid < 62) U1_s[tid] = gU1[tid];
    if (tid < 5)  U3_s[tid] = gU3[tid];
    if (tid < 9)  be_s[tid] = gbe[tid];
    if (tid < 9)  Ve_s[tid] = gVe[tid];
    if (tid < 3)  W1_s[tid] = gW1[tid];
    if (tid < 15) W2_s[tid] = gW2[tid];
    if (tid < 5)  W3_s[tid] = gW3[tid];
    if (tid < 5)  a_s[tid]  = ga[tid];
    if (tid < 64) { tb_s[tid]=gtb[tid]; rb_s[tid]=grb[tid]; gam_s[tid]=ggamma[tid]; bet_s[tid]=gbeta[tid]; }
    __syncthreads();

    // ---------------- Phase 1: temporal attention ----------------
    if (tid < 15) {                    // y[t][f] = sum_v x[t][v][f]*U1[v]
        int t = tid/5, f = tid%5;
        float s = 0.f;
        for (int v = 0; v < 62; v++) s += sx[t*310+v*5+f]*U1_s[v];
        y_s[t*5+f] = s;
    }
    if (tid < 186) {                   // rhs[v][t] = sum_f U3[f]*x[t][v][f]
        int v = tid/3, t = tid%3;
        const float* xr = sx + t*310 + v*5;
        float s = 0.f;
        #pragma unroll
        for (int f=0; f<5; f++) s += U3_s[f]*xr[f];
        rhs_s[v*3+t] = s;
    }
    __syncthreads();
    if (tid < 186) {                   // lhs[t][u] = sum_f y[t][f]*U2[f][u]
        int t = tid/62, u = tid%62;
        float s = 0.f;
        #pragma unroll
        for (int f=0; f<5; f++) s += y_s[t*5+f]*U2_s[f*62+u];
        lhs_s[t*62+u] = s;
    }
    __syncthreads();
    if (tid < 9) {                     // prod[t][u] = sum_v lhs[t][v]*rhs[v][u]
        int t = tid/3, u = tid%3;
        float s = 0.f;
        for (int v=0; v<62; v++) s += lhs_s[t*62+v]*rhs_s[v*3+u];
        prod_s[t*3+u] = s;
    }
    __syncthreads();
    if (tid < 9) {                     // E[t][u] = sum_s Ve[t][s]*sig(prod[s][u]+be[s][u])
        int t = tid/3, u = tid%3;
        float s = 0.f;
        #pragma unroll
        for (int k=0; k<3; k++) s += Ve_s[t*3+k]*sigmoidf(prod_s[k*3+u]+be_s[k*3+u]);
        E_s[t*3+u] = s;
    }
    __syncthreads();
    if (tid < 3) {                     // softmax over t per column u
        int u = tid;
        float m = fmaxf(E_s[u], fmaxf(E_s[3+u], E_s[6+u]));
        float e0=expf(E_s[u]-m), e1=expf(E_s[3+u]-m), e2=expf(E_s[6+u]-m);
        float inv = 1.0f/(e0+e1+e2);
        At_s[u]=e0*inv; At_s[3+u]=e1*inv; At_s[6+u]=e2*inv;
    }
    __syncthreads();
    for (int i = tid; i < 930; i += NT) {   // x_TAt[u][v][f]
        int u = i/310, r = i%310;
        sxT[i] = (sx[r]*At_s[u] + sx[310+r]*At_s[3+u] + sx[620+r]*At_s[6+u]) * 0.056796183f;
    }
    __syncthreads();

    // ---------------- Phase 2: spatial attention ----------------
    if (tid < 186) {                   // s_lhs[v][s]
        int v = tid/3, s = tid%3;
        float acc = 0.f;
        #pragma unroll
        for (int f=0; f<5; f++) {
            float yv = sxT[v*5+f]*W1_s[0] + sxT[310+v*5+f]*W1_s[1] + sxT[620+v*5+f]*W1_s[2];
            acc += yv*W2_s[f*3+s];
        }
        slhs_s[v*3+s] = acc;
    }
    if (tid < 186) {                   // s_rhs[t][v]
        int t = tid/62, v = tid%62;
        const float* xr = sxT + t*310 + v*5;
        float s = 0.f;
        #pragma unroll
        for (int f=0; f<5; f++) s += W3_s[f]*xr[f];
        srhs_s[t*62+v] = s;
    }
    __syncthreads();
    for (int i = tid; i < 3844; i += NT) {  // sig(s_prod+bs) [w][v], rowstride 64
        int w = i/62, v = i%62;
        float p = slhs_s[w*3]*srhs_s[v] + slhs_s[w*3+1]*srhs_s[62+v]
                + slhs_s[w*3+2]*srhs_s[124+v] + gbs[i];
        bufSg[w*64+v] = sigmoidf(p);
    }
    if (tid < 62) { bufSg[tid*64+62]=0.f; bufSg[tid*64+63]=0.f; }
    __syncthreads();
    {   // Sm[u][v] = sum_w Vs[u][w]*sig[w][v] ; 1x8 register tile + float4 loads
        int u = tid>>3, vq = tid&7;
        if (u < 62) {
            float acc[8];
            #pragma unroll
            for (int k=0;k<8;k++) acc[k]=0.f;
            for (int w=0; w<62; w++) {
                float vsv = Vs_s[u*62+w];
                const float4* rowp = reinterpret_cast<const float4*>(bufSg + w*64 + vq*8);
                float4 s0 = rowp[0], s1 = rowp[1];
                acc[0] += vsv*s0.x; acc[1] += vsv*s0.y; acc[2] += vsv*s0.z; acc[3] += vsv*s0.w;
                acc[4] += vsv*s1.x; acc[5] += vsv*s1.y; acc[6] += vsv*s1.z; acc[7] += vsv*s1.w;
            }
            #pragma unroll
            for (int k=0;k<8;k++) {
                int v = vq*8+k;
                if (v < 62) bufAt[u*62+v] = acc[k];
            }
        }
    }
    __syncthreads();
    {   // softmax over u per column v: 8 threads per column + shfl
        int v = tid>>3, g = tid&7;
        bool act = (v < 62);
        float m = -1e30f;
        if (act) for (int u=g; u<62; u+=8) m = fmaxf(m, bufAt[u*62+v]);
        #pragma unroll
        for (int o=4; o; o>>=1) m = fmaxf(m, __shfl_xor_sync(0xffffffffu, m, o));
        float ssum = 0.f;
        if (act) for (int u=g; u<62; u+=8) { float e = expf(bufAt[u*62+v]-m); bufAt[u*62+v]=e; ssum+=e; }
        #pragma unroll
        for (int o=4; o; o>>=1) ssum += __shfl_xor_sync(0xffffffffu, ssum, o);
        float inv = 1.0f/ssum;
        if (act) for (int u=g; u<62; u+=8) bufAt[u*62+v] *= inv;
    }
    __syncthreads();

    // ---------------- Phase 3: S matrix + losses ----------------
    const float* xm = sx + 310;        // x[:,1]
    {
        float a0=a_s[0],a1=a_s[1],a2=a_s[2],a3=a_s[3],a4=a_s[4];
        for (int i = tid; i < 3844; i += NT) {
            int ii = i/62, jj = i%62;
            const float* xi = xm + ii*5; const float* xj = xm + jj*5;
            float e = fabsf(xi[0]-xj[0])*a0 + fabsf(xi[1]-xj[1])*a1 + fabsf(xi[2]-xj[2])*a2
                    + fabsf(xi[3]-xj[3])*a3 + fabsf(xi[4]-xj[4])*a4;
            bufS[i] = expf(fmaxf(e, 0.0f));
        }
    }
    __syncthreads();
    {   // colsum of tmpS: 8 threads per column + shfl
        int j = tid>>3, g = tid&7;
        bool act = (j < 62);
        float cs = 0.f;
        if (act) for (int i=g; i<62; i+=8) cs += bufS[i*62+j];
        #pragma unroll
        for (int o=4; o; o>>=1) cs += __shfl_xor_sync(0xffffffffu, cs, o);
        if (act && g==0) colsum[j] = cs;
    }
    __syncthreads();
    for (int i = tid; i < 3844; i += NT) {
        float s = bufS[i] / colsum[i%62];
        bufS[i] = s;
        out[S_BASE + (size_t)b*3844 + i] = s;
    }
    __syncthreads();
    {   // Dg[j] = colsum of normalized S, and d2row[j]
        int j = tid>>3, g = tid&7;
        bool act = (j < 62);
        float cs = 0.f, dd = 0.f;
        if (act) {
            const float* xj = xm + j*5;
            for (int i=g; i<62; i+=8) {
                cs += bufS[i*62+j];
                const float* xi = xm + i*5;
                #pragma unroll
                for (int f=0; f<5; f++) { float d = xj[f]-xi[f]; dd += d*d; }
            }
        }
        #pragma unroll
        for (int o=4; o; o>>=1) {
            cs += __shfl_xor_sync(0xffffffffu, cs, o);
            dd += __shfl_xor_sync(0xffffffffu, dd, o);
        }
        if (act && g==0) { DgS_s[j] = cs; d2s_s[j] = dd; }
    }
    {   // Sloss block partial
        float sl = 0.f;
        for (int i = tid; i < 3844; i += NT) sl += bufS[i]*bufS[i];
        red_s[tid] = sl;
    }
    __syncthreads();
    for (int s = NT/2; s > 0; s >>= 1) {
        if (tid < s) red_s[tid] += red_s[tid+s];
        __syncthreads();
    }
    if (tid == 0) {
        atomicAdd(out + XR_ELEMS, red_s[0] * (ALPHA/(float)NBATCH));
        float dp = 0.f;
        for (int j=0; j<62; j++) dp += DgS_s[j]*d2s_s[j];
        atomicAdd(out + XR_ELEMS + 1, dp * ALPHA);
    }

    // ---------------- Phase 4: cheb * spatial_At * x * Theta -> spatial_gcn ----------------
    if (tid < 372) {
        int half = (tid >= 186);
        int r = tid - half*186;
        int t = r/62, v = r%62;
        float acc[15];
        #pragma unroll
        for (int k=0;k<15;k++) acc[k]=0.f;
        float dgm1 = DgS_s[v] - 1.0f;
        for (int u=0; u<62; u++) {
            float s  = bufS[u*62+v];
            float at = bufAt[u*62+v];
            float delta = (u==v) ? 1.0f : 0.0f;
            float lt = dgm1*delta - s;                 // L_t[u][v]
            float c2 = 2.0f*lt*lt - delta;             // cheb2 (elementwise!)
            float t0 = delta*at, t1 = lt*at, t2 = c2*at;
            const float* xr = sx + t*310 + u*5;
            #pragma unroll
            for (int f=0; f<5; f++) {
                float xv = xr[f];
                acc[f]    += t0*xv;
                acc[5+f]  += t1*xv;
                acc[10+f] += t2*xv;
            }
        }
        int o0 = half*32;
        #pragma unroll 4
        for (int o=o0; o<o0+32; o++) {
            float z = 0.f;
            #pragma unroll
            for (int kf=0; kf<15; kf++) z += acc[kf]*Th_s[kf*64+o];
            sg[t*4096 + o*64 + v] = fmaxf(z, 0.0f);
        }
    }
    for (int i = tid; i < 192; i += NT) {   // zero sg pad cols 62,63
        int t = i/64, c = i%64;
        sg[t*4096 + c*64 + 62] = 0.f;
        sg[t*4096 + c*64 + 63] = 0.f;
    }
    __syncthreads();

    // ---------------- Phase 5: temporal conv + residual + relu ----------------
    {
        int o2 = tid>>3, vq = tid&7;
        float acc[8];
        #pragma unroll
        for (int k=0;k<8;k++) acc[k]=0.f;
        for (int c=0; c<64; c++) {
            const float* twp = tw_s + (o2*64+c)*3;
            #pragma unroll
            for (int t=0; t<3; t++) {
                float w = twp[t];
                const float4* rowp = reinterpret_cast<const float4*>(sg + t*4096 + c*64 + vq*8);
                float4 s0 = rowp[0], s1 = rowp[1];
                acc[0] += w*s0.x; acc[1] += w*s0.y; acc[2] += w*s0.z; acc[3] += w*s0.w;
                acc[4] += w*s1.x; acc[5] += w*s1.y; acc[6] += w*s1.z; acc[7] += w*s1.w;
            }
        }
        float tbv = tb_s[o2], rbv = rb_s[o2];
        const float* rwp = rw_s + o2*5;
        #pragma unroll
        for (int k=0;k<8;k++) {
            int v = vq*8+k;
            if (v < 62) {
                float tcv = (acc[k] + tbv) * 0.25819889f;   // /sqrt(15)
                const float* x0 = sx + v*5;                 // x[b,0,v,:]
                float resv = rbv + x0[0]*rwp[0]+x0[1]*rwp[1]+x0[2]*rwp[2]
                                 + x0[3]*rwp[3]+x0[4]*rwp[4];
                zb[v*65+o2] = fmaxf(resv + tcv, 0.0f);
            }
        }
    }
    __syncthreads();

    // ---------------- Phase 6: LayerNorm over H2 + writeback ----------------
    {   // mean/var over o: 8 threads per v + shfl
        int v = tid>>3, g = tid&7;
        bool act = (v < 62);
        float s = 0.f;
        if (act) for (int o=g; o<64; o+=8) s += zb[v*65+o];
        #pragma unroll
        for (int o=4; o; o>>=1) s += __shfl_xor_sync(0xffffffffu, s, o);
        float mu = s * (1.0f/64.0f);
        float vv = 0.f;
        if (act) for (int o=g; o<64; o+=8) { float d = zb[v*65+o]-mu; vv += d*d; }
        #pragma unroll
        for (int o=4; o; o>>=1) vv += __shfl_xor_sync(0xffffffffu, vv, o);
        vv *= (1.0f/64.0f);
        if (act && g==0) { mu_s[v] = mu; iv_s[v] = rsqrtf(vv + LN_EPS); }
    }
    __syncthreads();
    for (int i = tid; i < 3968; i += NT) {
        int v = i>>6, o = i&63;
        float val = (zb[v*65+o]-mu_s[v])*iv_s[v]*gam_s[o] + bet_s[o];
        out[(size_t)b*3968 + i] = val;
    }
}

#define SMEM_BYTES (49600*4)

extern "C" void kernel_launch(void* const* d_in, const int* in_sizes, int n_in,
                              void* d_out, int out_size) {
    const float* x     = (const float*)d_in[0];
    const float* U1    = (const float*)d_in[1];
    const float* U2    = (const float*)d_in[2];
    const float* U3    = (const float*)d_in[3];
    const float* be    = (const float*)d_in[4];
    const float* Ve    = (const float*)d_in[5];
    const float* W1    = (const float*)d_in[6];
    const float* W2    = (const float*)d_in[7];
    const float* W3    = (const float*)d_in[8];
    const float* bs    = (const float*)d_in[9];
    const float* Vs    = (const float*)d_in[10];
    const float* a     = (const float*)d_in[11];
    const float* Theta = (const float*)d_in[12];
    const float* tw    = (const float*)d_in[13];
    const float* tb    = (const float*)d_in[14];
    const float* rw    = (const float*)d_in[15];
    const float* rb    = (const float*)d_in[16];
    const float* gamma = (const float*)d_in[17];
    const float* beta  = (const float*)d_in[18];
    float* out = (float*)d_out;

    cudaFuncSetAttribute(stgcn_kernel, cudaFuncAttributeMaxDynamicSharedMemorySize, SMEM_BYTES);

    zero_loss_kernel<<<1, 32>>>(out);
    stgcn_kernel<<<NBATCH, NT, SMEM_BYTES>>>(x, U1, U2, U3, be, Ve, W1, W2, W3,
                                             bs, Vs, a, Theta, tw, tb, rw, rb,
                                             gamma, beta, out);
}

// round 3
// speedup vs baseline: 1.6758x; 1.3526x over previous
#include <cuda_runtime.h>
#include <math.h>

#define NBATCH 2048
#define ALPHA 1e-4f
#define LN_EPS 1e-5f
#define NT 512

#define XR_ELEMS (NBATCH*62*64)      /* 8126464 */
#define S_BASE   (XR_ELEMS + 2)

__global__ void zero_loss_kernel(float* out) {
    if (threadIdx.x < 2) out[XR_ELEMS + threadIdx.x] = 0.0f;
}

__device__ __forceinline__ float sigmoidf(float x){ return 1.0f/(1.0f+expf(-x)); }

__global__ void __launch_bounds__(NT,1) stgcn_kernel(
    const float* __restrict__ gx, const float* __restrict__ gU1,
    const float* __restrict__ gU2, const float* __restrict__ gU3,
    const float* __restrict__ gbe, const float* __restrict__ gVe,
    const float* __restrict__ gW1, const float* __restrict__ gW2,
    const float* __restrict__ gW3, const float* __restrict__ gbs,
    const float* __restrict__ gVs, const float* __restrict__ ga,
    const float* __restrict__ gTheta, const float* __restrict__ gtw,
    const float* __restrict__ gtb, const float* __restrict__ grw,
    const float* __restrict__ grb, const float* __restrict__ ggamma,
    const float* __restrict__ gbeta, float* __restrict__ out)
{
    extern __shared__ float smarr[];
    const int tid = threadIdx.x;
    const int b = blockIdx.x;

    float* sx    = smarr;              // 932
    float* sxT   = sx   + 932;         // 932
    float* bufS  = sxT  + 932;         // 3844
    float* bufAt = bufS + 3844;        // 3848
    float* bufSg = bufAt+ 3848;        // 3968  (reused as accbuf in phase 4)
    float* Vs_s  = bufSg+ 3968;        // 3844  (accbuf overflow region)
    float* tw_s  = Vs_s + 3844;        // 12288 [o][c][t]
    float* Th_s  = tw_s + 12288;       // 960  [kf][o]
    float* sg    = Th_s + 960;         // 12288 [t][c][v] rowstride 64
    float* zb    = sg   + 12288;       // 4032 z [v][o] rowstride 65
    float* U1_s  = zb   + 4032;        // 64
    float* U2_s  = U1_s + 64;          // 312
    float* U3_s  = U2_s + 312;         // 8
    float* be_s  = U3_s + 8;           // 12
    float* Ve_s  = be_s + 12;          // 12
    float* W1_s  = Ve_s + 12;          // 4
    float* W2_s  = W1_s + 4;           // 16
    float* W3_s  = W2_s + 16;          // 8
    float* a_s   = W3_s + 8;           // 8
    float* tb_s  = a_s  + 8;           // 64
    float* rw_s  = tb_s + 64;          // 320
    float* rb_s  = rw_s + 320;         // 64
    float* gam_s = rb_s + 64;          // 64
    float* bet_s = gam_s+ 64;          // 64
    float* y_s   = bet_s+ 64;          // 16
    float* lhs_s = y_s  + 16;          // 188
    float* rhs_s = lhs_s+ 188;         // 188
    float* prod_s= rhs_s+ 188;         // 12
    float* E_s   = prod_s+12;          // 12
    float* At_s  = E_s  + 12;          // 12
    float* slhs_s= At_s + 12;          // 188
    float* srhs_s= slhs_s+188;         // 188
    float* colsum= srhs_s+188;         // 64  (stores reciprocal)
    float* DgS_s = colsum+ 64;         // 64
    float* d2s_s = DgS_s + 64;         // 64
    float* mu_s  = d2s_s + 64;         // 64
    float* iv_s  = mu_s  + 64;         // 64
    float* red_s = iv_s  + 64;         // 512
    float* accbuf = bufSg;             // 5580 floats (fits bufSg+Vs_s = 7812)

    // ---------------- Phase 0: stage inputs ----------------
    for (int i = tid; i < 930;   i += NT) sx[i]   = gx[(size_t)b*930 + i];
    for (int i = tid; i < 3844;  i += NT) Vs_s[i] = gVs[i];
    for (int i = tid; i < 12288; i += NT) tw_s[i] = gtw[i];
    for (int i = tid; i < 960;   i += NT) Th_s[i] = gTheta[i];
    for (int i = tid; i < 310;   i += NT) U2_s[i] = gU2[i];
    for (int i = tid; i < 320;   i += NT) rw_s[i] = grw[i];
    if (tid < 62) U1_s[tid] = gU1[tid];
    if (tid < 5)  U3_s[tid] = gU3[tid];
    if (tid < 9)  be_s[tid] = gbe[tid];
    if (tid < 9)  Ve_s[tid] = gVe[tid];
    if (tid < 3)  W1_s[tid] = gW1[tid];
    if (tid < 15) W2_s[tid] = gW2[tid];
    if (tid < 5)  W3_s[tid] = gW3[tid];
    if (tid < 5)  a_s[tid]  = ga[tid];
    if (tid < 64) { tb_s[tid]=gtb[tid]; rb_s[tid]=grb[tid]; gam_s[tid]=ggamma[tid]; bet_s[tid]=gbeta[tid]; }
    __syncthreads();

    // ---------------- Phase 1: temporal attention ----------------
    if (tid < 15) {
        int t = tid/5, f = tid%5;
        float s = 0.f;
        for (int v = 0; v < 62; v++) s += sx[t*310+v*5+f]*U1_s[v];
        y_s[t*5+f] = s;
    }
    if (tid < 186) {
        int v = tid/3, t = tid%3;
        const float* xr = sx + t*310 + v*5;
        float s = 0.f;
        #pragma unroll
        for (int f=0; f<5; f++) s += U3_s[f]*xr[f];
        rhs_s[v*3+t] = s;
    }
    __syncthreads();
    if (tid < 186) {
        int t = tid/62, u = tid%62;
        float s = 0.f;
        #pragma unroll
        for (int f=0; f<5; f++) s += y_s[t*5+f]*U2_s[f*62+u];
        lhs_s[t*62+u] = s;
    }
    __syncthreads();
    if (tid < 9) {
        int t = tid/3, u = tid%3;
        float s = 0.f;
        for (int v=0; v<62; v++) s += lhs_s[t*62+v]*rhs_s[v*3+u];
        prod_s[t*3+u] = s;
    }
    __syncthreads();
    if (tid < 9) {
        int t = tid/3, u = tid%3;
        float s = 0.f;
        #pragma unroll
        for (int k=0; k<3; k++) s += Ve_s[t*3+k]*sigmoidf(prod_s[k*3+u]+be_s[k*3+u]);
        E_s[t*3+u] = s;
    }
    __syncthreads();
    if (tid < 3) {
        int u = tid;
        float m = fmaxf(E_s[u], fmaxf(E_s[3+u], E_s[6+u]));
        float e0=expf(E_s[u]-m), e1=expf(E_s[3+u]-m), e2=expf(E_s[6+u]-m);
        float inv = 1.0f/(e0+e1+e2);
        At_s[u]=e0*inv; At_s[3+u]=e1*inv; At_s[6+u]=e2*inv;
    }
    __syncthreads();
    for (int i = tid; i < 930; i += NT) {
        int u = i/310, r = i%310;
        sxT[i] = (sx[r]*At_s[u] + sx[310+r]*At_s[3+u] + sx[620+r]*At_s[6+u]) * 0.056796183f;
    }
    __syncthreads();

    // ---------------- Phase 2: spatial attention ----------------
    if (tid < 186) {
        int v = tid/3, s = tid%3;
        float acc = 0.f;
        #pragma unroll
        for (int f=0; f<5; f++) {
            float yv = sxT[v*5+f]*W1_s[0] + sxT[310+v*5+f]*W1_s[1] + sxT[620+v*5+f]*W1_s[2];
            acc += yv*W2_s[f*3+s];
        }
        slhs_s[v*3+s] = acc;
    }
    if (tid < 186) {
        int t = tid/62, v = tid%62;
        const float* xr = sxT + t*310 + v*5;
        float s = 0.f;
        #pragma unroll
        for (int f=0; f<5; f++) s += W3_s[f]*xr[f];
        srhs_s[t*62+v] = s;
    }
    __syncthreads();
    for (int i = tid; i < 3844; i += NT) {   // sig(s_prod+bs) [w][v], rowstride 64
        int w = i/62, v = i%62;
        float p = slhs_s[w*3]*srhs_s[v] + slhs_s[w*3+1]*srhs_s[62+v]
                + slhs_s[w*3+2]*srhs_s[124+v] + gbs[i];
        bufSg[w*64+v] = sigmoidf(p);
    }
    if (tid < 62) { bufSg[tid*64+62]=0.f; bufSg[tid*64+63]=0.f; }
    __syncthreads();
    {   // Sm[u][v] = sum_w Vs[u][w]*sig[w][v] ; 2u x 8v tile, 2-way w-split + shfl
        int u2 = tid>>4;            // 0..31
        int rem = tid&15;
        int vq = rem>>1;            // 0..7
        int ws = rem&1;
        int u0 = u2*2;
        bool uvalid = (u0 < 62);
        int ua = uvalid ? u0 : 0;
        float acc[16];
        #pragma unroll
        for (int k=0;k<16;k++) acc[k]=0.f;
        for (int wi=0; wi<31; wi++) {
            int w = ws*31+wi;
            float va = Vs_s[ua*62+w];
            float vb = Vs_s[(ua+1)*62+w];
            const float4* rowp = reinterpret_cast<const float4*>(bufSg + w*64 + vq*8);
            float4 s0 = rowp[0], s1 = rowp[1];
            float sv[8] = {s0.x,s0.y,s0.z,s0.w,s1.x,s1.y,s1.z,s1.w};
            #pragma unroll
            for (int j=0;j<8;j++) { acc[j] += va*sv[j]; acc[8+j] += vb*sv[j]; }
        }
        #pragma unroll
        for (int k=0;k<16;k++) acc[k] += __shfl_xor_sync(0xffffffffu, acc[k], 1);
        if (uvalid) {
            #pragma unroll
            for (int dv=0; dv<4; dv++) {
                int v = vq*8 + ws*4 + dv;
                if (v < 62) {
                    bufAt[ua*62+v]     = acc[ws*4+dv];
                    bufAt[(ua+1)*62+v] = acc[8+ws*4+dv];
                }
            }
        }
    }
    __syncthreads();
    {   // softmax over u per column v: 8 threads per column + shfl
        int v = tid>>3, g = tid&7;
        bool act = (v < 62);
        float m = -1e30f;
        if (act) for (int u=g; u<62; u+=8) m = fmaxf(m, bufAt[u*62+v]);
        #pragma unroll
        for (int o=4; o; o>>=1) m = fmaxf(m, __shfl_xor_sync(0xffffffffu, m, o));
        float ssum = 0.f;
        if (act) for (int u=g; u<62; u+=8) { float e = expf(bufAt[u*62+v]-m); bufAt[u*62+v]=e; ssum+=e; }
        #pragma unroll
        for (int o=4; o; o>>=1) ssum += __shfl_xor_sync(0xffffffffu, ssum, o);
        float inv = 1.0f/ssum;
        if (act) for (int u=g; u<62; u+=8) bufAt[u*62+v] *= inv;
    }
    __syncthreads();

    // ---------------- Phase 3: S matrix + losses ----------------
    const float* xm = sx + 310;
    {
        float a0=a_s[0],a1=a_s[1],a2=a_s[2],a3=a_s[3],a4=a_s[4];
        for (int i = tid; i < 3844; i += NT) {
            int ii = i/62, jj = i%62;
            const float* xi = xm + ii*5; const float* xj = xm + jj*5;
            float e = fabsf(xi[0]-xj[0])*a0 + fabsf(xi[1]-xj[1])*a1 + fabsf(xi[2]-xj[2])*a2
                    + fabsf(xi[3]-xj[3])*a3 + fabsf(xi[4]-xj[4])*a4;
            bufS[i] = expf(fmaxf(e, 0.0f));
        }
    }
    __syncthreads();
    {   // column reciprocal
        int j = tid>>3, g = tid&7;
        bool act = (j < 62);
        float cs = 0.f;
        if (act) for (int i=g; i<62; i+=8) cs += bufS[i*62+j];
        #pragma unroll
        for (int o=4; o; o>>=1) cs += __shfl_xor_sync(0xffffffffu, cs, o);
        if (act && g==0) colsum[j] = 1.0f/cs;
    }
    __syncthreads();
    for (int i = tid; i < 3844; i += NT) {
        float s = bufS[i] * colsum[i%62];
        bufS[i] = s;
        out[S_BASE + (size_t)b*3844 + i] = s;
    }
    __syncthreads();
    {   // Dg[j] (colsum of normalized S) and d2row[j]
        int j = tid>>3, g = tid&7;
        bool act = (j < 62);
        float cs = 0.f, dd = 0.f;
        if (act) {
            const float* xj = xm + j*5;
            for (int i=g; i<62; i+=8) {
                cs += bufS[i*62+j];
                const float* xi = xm + i*5;
                #pragma unroll
                for (int f=0; f<5; f++) { float d = xj[f]-xi[f]; dd += d*d; }
            }
        }
        #pragma unroll
        for (int o=4; o; o>>=1) {
            cs += __shfl_xor_sync(0xffffffffu, cs, o);
            dd += __shfl_xor_sync(0xffffffffu, dd, o);
        }
        if (act && g==0) { DgS_s[j] = cs; d2s_s[j] = dd; }
    }
    {   // Sloss block partial
        float sl = 0.f;
        for (int i = tid; i < 3844; i += NT) sl += bufS[i]*bufS[i];
        red_s[tid] = sl;
    }
    __syncthreads();
    for (int s = NT/2; s > 0; s >>= 1) {
        if (tid < s) red_s[tid] += red_s[tid+s];
        __syncthreads();
    }
    if (tid == 0) {
        atomicAdd(out + XR_ELEMS, red_s[0] * (ALPHA/(float)NBATCH));
        float dp = 0.f;
        for (int j=0; j<62; j++) dp += DgS_s[j]*d2s_s[j];
        atomicAdd(out + XR_ELEMS + 1, dp * ALPHA);
    }
    __syncthreads();   // protect bufSg->accbuf reuse ordering (Sloss used bufS only; sync for accbuf write)

    // ---------------- Phase 4a: partial cheb accumulators (u-split halves) ----------------
    if (tid < 372) {
        int half = (tid >= 186);
        int r = tid - half*186;
        int t = r/62, v = r%62;
        float acc[15];
        #pragma unroll
        for (int k=0;k<15;k++) acc[k]=0.f;
        float dgm1 = DgS_s[v] - 1.0f;
        int u0 = half*31;
        for (int ui=0; ui<31; ui++) {
            int u = u0+ui;
            float s  = bufS[u*62+v];
            float at = bufAt[u*62+v];
            float delta = (u==v) ? 1.0f : 0.0f;
            float lt = dgm1*delta - s;
            float c2 = 2.0f*lt*lt - delta;
            float t0 = delta*at, t1 = lt*at, t2 = c2*at;
            const float* xr = sx + t*310 + u*5;
            #pragma unroll
            for (int f=0; f<5; f++) {
                float xv = xr[f];
                acc[f]    += t0*xv;
                acc[5+f]  += t1*xv;
                acc[10+f] += t2*xv;
            }
        }
        int tv = t*62+v;
        #pragma unroll
        for (int kf=0; kf<15; kf++) accbuf[kf*372 + half*186 + tv] = acc[kf];
    }
    __syncthreads();

    // ---------------- Phase 4b: Theta contraction -> spatial_gcn (2 v per thread) ----------------
    if (tid < 186) {
        int t = tid/62;
        int r = tid%62;
        int vp = r>>1, oh = r&1;
        int v0 = vp*2, v1 = v0+1;
        int tv0 = t*62+v0, tv1 = tv0+1;
        float a0[15], a1[15];
        #pragma unroll
        for (int kf=0; kf<15; kf++) {
            a0[kf] = accbuf[kf*372 + tv0] + accbuf[kf*372 + 186 + tv0];
            a1[kf] = accbuf[kf*372 + tv1] + accbuf[kf*372 + 186 + tv1];
        }
        int ob = oh*32;
        #pragma unroll 4
        for (int oi=0; oi<32; oi++) {
            int o = ob+oi;
            float z0 = 0.f, z1 = 0.f;
            #pragma unroll
            for (int kf=0; kf<15; kf++) {
                float th = Th_s[kf*64+o];
                z0 += a0[kf]*th; z1 += a1[kf]*th;
            }
            sg[t*4096 + o*64 + v0] = fmaxf(z0, 0.0f);
            sg[t*4096 + o*64 + v1] = fmaxf(z1, 0.0f);
        }
    }
    for (int i = tid; i < 192; i += NT) {   // zero sg pad cols 62,63
        int t = i/64, c = i%64;
        sg[t*4096 + c*64 + 62] = 0.f;
        sg[t*4096 + c*64 + 63] = 0.f;
    }
    __syncthreads();

    // ---------------- Phase 5: temporal conv (4o x 8v tile, 4-way k-split) ----------------
    {
        int o4  = tid>>5;           // 0..15 : warp-uniform o-group
        int rem = tid&31;
        int vq  = rem>>2;           // 0..7
        int ks  = rem&3;            // 0..3  : c-split
        int ob  = o4*4;
        float acc[32];              // [oi*8+vj]
        #pragma unroll
        for (int k=0;k<32;k++) acc[k]=0.f;
        int c0 = ks*16;
        for (int ci=0; ci<16; ci++) {
            int c = c0+ci;
            #pragma unroll
            for (int t=0; t<3; t++) {
                const float4* rowp = reinterpret_cast<const float4*>(sg + t*4096 + c*64 + vq*8);
                float4 s0 = rowp[0], s1 = rowp[1];
                float sv[8] = {s0.x,s0.y,s0.z,s0.w,s1.x,s1.y,s1.z,s1.w};
                float wv[4];
                #pragma unroll
                for (int oi=0; oi<4; oi++) wv[oi] = tw_s[((ob+oi)*64+c)*3+t];
                #pragma unroll
                for (int oi=0; oi<4; oi++)
                    #pragma unroll
                    for (int vj=0; vj<8; vj++)
                        acc[oi*8+vj] += wv[oi]*sv[vj];
            }
        }
        // reduce the 4 c-split partials across lanes (ks in bits 0-1)
        #pragma unroll
        for (int k=0;k<32;k++) {
            acc[k] += __shfl_xor_sync(0xffffffffu, acc[k], 1);
            acc[k] += __shfl_xor_sync(0xffffffffu, acc[k], 2);
        }
        // every lane now holds full sums; lane ks writes vj = 2ks, 2ks+1
        #pragma unroll
        for (int dv=0; dv<2; dv++) {
            int vj = ks*2+dv;
            int v = vq*8+vj;
            if (v < 62) {
                const float* x0 = sx + v*5;
                float xa=x0[0], xb=x0[1], xc=x0[2], xd=x0[3], xe=x0[4];
                #pragma unroll
                for (int oi=0; oi<4; oi++) {
                    int o = ob+oi;
                    float tcv = (acc[oi*8+vj] + tb_s[o]) * 0.25819889f;
                    const float* rwp = rw_s + o*5;
                    float resv = rb_s[o] + xa*rwp[0]+xb*rwp[1]+xc*rwp[2]+xd*rwp[3]+xe*rwp[4];
                    zb[v*65+o] = fmaxf(resv + tcv, 0.0f);
                }
            }
        }
    }
    __syncthreads();

    // ---------------- Phase 6: LayerNorm over H2 + writeback ----------------
    {
        int v = tid>>3, g = tid&7;
        bool act = (v < 62);
        float s = 0.f;
        if (act) for (int o=g; o<64; o+=8) s += zb[v*65+o];
        #pragma unroll
        for (int o=4; o; o>>=1) s += __shfl_xor_sync(0xffffffffu, s, o);
        float mu = s * (1.0f/64.0f);
        float vv = 0.f;
        if (act) for (int o=g; o<64; o+=8) { float d = zb[v*65+o]-mu; vv += d*d; }
        #pragma unroll
        for (int o=4; o; o>>=1) vv += __shfl_xor_sync(0xffffffffu, vv, o);
        vv *= (1.0f/64.0f);
        if (act && g==0) { mu_s[v] = mu; iv_s[v] = rsqrtf(vv + LN_EPS); }
    }
    __syncthreads();
    for (int i = tid; i < 3968; i += NT) {
        int v = i>>6, o = i&63;
        float val = (zb[v*65+o]-mu_s[v])*iv_s[v]*gam_s[o] + bet_s[o];
        out[(size_t)b*3968 + i] = val;
    }
}

#define SMEM_BYTES (49600*4)

extern "C" void kernel_launch(void* const* d_in, const int* in_sizes, int n_in,
                              void* d_out, int out_size) {
    const float* x     = (const float*)d_in[0];
    const float* U1    = (const float*)d_in[1];
    const float* U2    = (const float*)d_in[2];
    const float* U3    = (const float*)d_in[3];
    const float* be    = (const float*)d_in[4];
    const float* Ve    = (const float*)d_in[5];
    const float* W1    = (const float*)d_in[6];
    const float* W2    = (const float*)d_in[7];
    const float* W3    = (const float*)d_in[8];
    const float* bs    = (const float*)d_in[9];
    const float* Vs    = (const float*)d_in[10];
    const float* a     = (const float*)d_in[11];
    const float* Theta = (const float*)d_in[12];
    const float* tw    = (const float*)d_in[13];
    const float* tb    = (const float*)d_in[14];
    const float* rw    = (const float*)d_in[15];
    const float* rb    = (const float*)d_in[16];
    const float* gamma = (const float*)d_in[17];
    const float* beta  = (const float*)d_in[18];
    float* out = (float*)d_out;

    cudaFuncSetAttribute(stgcn_kernel, cudaFuncAttributeMaxDynamicSharedMemorySize, SMEM_BYTES);

    zero_loss_kernel<<<1, 32>>>(out);
    stgcn_kernel<<<NBATCH, NT, SMEM_BYTES>>>(x, U1, U2, U3, be, Ve, W1, W2, W3,
                                             bs, Vs, a, Theta, tw, tb, rw, rb,
                                             gamma, beta, out);
}

// round 4
// speedup vs baseline: 1.8156x; 1.0834x over previous
#include <cuda_runtime.h>
#include <math.h>

#define NBATCH 2048
#define ALPHA 1e-4f
#define LN_EPS 1e-5f
#define NT 512

#define XR_ELEMS (NBATCH*62*64)      /* 8126464 */
#define S_BASE   (XR_ELEMS + 2)

// Scratch: per-batch 15 x 372 cheb partial accumulators, and transposed tw.
__device__ float g_acc[NBATCH*5580];     // [b][kf][half*186 + t*62+v]
__device__ float g_twt[12288];           // [t][c][o]

__device__ __forceinline__ float fsig(float x){ return __fdividef(1.0f, 1.0f+__expf(-x)); }

__global__ void prep_kernel(const float* __restrict__ gtw, float* __restrict__ out) {
    int i = blockIdx.x*256 + threadIdx.x;
    if (i < 12288) {
        int o = i/192, c = (i%192)/3, t = i%3;
        g_twt[(t*64+c)*64+o] = gtw[i];
    }
    if (i < 2) out[XR_ELEMS + i] = 0.0f;
}

// ============================ KERNEL A: phases 0-4a ============================
__global__ void __launch_bounds__(NT,2) stgcn_a(
    const float* __restrict__ gx, const float* __restrict__ gU1,
    const float* __restrict__ gU2, const float* __restrict__ gU3,
    const float* __restrict__ gbe, const float* __restrict__ gVe,
    const float* __restrict__ gW1, const float* __restrict__ gW2,
    const float* __restrict__ gW3, const float* __restrict__ gbs,
    const float* __restrict__ gVs, const float* __restrict__ ga,
    float* __restrict__ out)
{
    extern __shared__ float smarr[];
    const int tid = threadIdx.x;
    const int b = blockIdx.x;

    float* sx    = smarr;              // 932
    float* sxT   = sx   + 932;         // 932
    float* bufS  = sxT  + 932;         // 3844
    float* bufAt = bufS + 3844;        // 3848
    float* bufSg = bufAt+ 3848;        // 3968
    float* Vs_s  = bufSg+ 3968;        // 3844
    float* U1_s  = Vs_s + 3844;        // 64
    float* U2_s  = U1_s + 64;          // 312
    float* U3_s  = U2_s + 312;         // 8
    float* be_s  = U3_s + 8;           // 12
    float* Ve_s  = be_s + 12;          // 12
    float* W1_s  = Ve_s + 12;          // 4
    float* W2_s  = W1_s + 4;           // 16
    float* W3_s  = W2_s + 16;          // 8
    float* a_s   = W3_s + 8;           // 8
    float* y_s   = a_s  + 8;           // 16
    float* lhs_s = y_s  + 16;          // 188
    float* rhs_s = lhs_s+ 188;         // 188
    float* prod_s= rhs_s+ 188;         // 12
    float* E_s   = prod_s+12;          // 12
    float* At_s  = E_s  + 12;          // 12
    float* slhs_s= At_s + 12;          // 188
    float* srhs_s= slhs_s+188;         // 188
    float* colsum= srhs_s+188;         // 64
    float* DgS_s = colsum+ 64;         // 64
    float* d2s_s = DgS_s + 64;         // 64
    float* red_s = d2s_s + 64;         // 512

    // ---------------- Phase 0: stage inputs ----------------
    for (int i = tid; i < 930;  i += NT) sx[i]   = gx[(size_t)b*930 + i];
    for (int i = tid; i < 3844; i += NT) Vs_s[i] = gVs[i];
    for (int i = tid; i < 310;  i += NT) U2_s[i] = gU2[i];
    if (tid < 62) U1_s[tid] = gU1[tid];
    if (tid < 5)  U3_s[tid] = gU3[tid];
    if (tid < 9)  be_s[tid] = gbe[tid];
    if (tid < 9)  Ve_s[tid] = gVe[tid];
    if (tid < 3)  W1_s[tid] = gW1[tid];
    if (tid < 15) W2_s[tid] = gW2[tid];
    if (tid < 5)  W3_s[tid] = gW3[tid];
    if (tid < 5)  a_s[tid]  = ga[tid];
    __syncthreads();

    // ---------------- Phase 1: temporal attention ----------------
    if (tid < 15) {
        int t = tid/5, f = tid%5;
        float s = 0.f;
        for (int v = 0; v < 62; v++) s += sx[t*310+v*5+f]*U1_s[v];
        y_s[t*5+f] = s;
    }
    if (tid < 186) {
        int v = tid/3, t = tid%3;
        const float* xr = sx + t*310 + v*5;
        float s = 0.f;
        #pragma unroll
        for (int f=0; f<5; f++) s += U3_s[f]*xr[f];
        rhs_s[v*3+t] = s;
    }
    __syncthreads();
    if (tid < 186) {
        int t = tid/62, u = tid%62;
        float s = 0.f;
        #pragma unroll
        for (int f=0; f<5; f++) s += y_s[t*5+f]*U2_s[f*62+u];
        lhs_s[t*62+u] = s;
    }
    __syncthreads();
    if (tid < 9) {
        int t = tid/3, u = tid%3;
        float s = 0.f;
        for (int v=0; v<62; v++) s += lhs_s[t*62+v]*rhs_s[v*3+u];
        prod_s[t*3+u] = s;
    }
    __syncthreads();
    if (tid < 9) {
        int t = tid/3, u = tid%3;
        float s = 0.f;
        #pragma unroll
        for (int k=0; k<3; k++) s += Ve_s[t*3+k]*fsig(prod_s[k*3+u]+be_s[k*3+u]);
        E_s[t*3+u] = s;
    }
    __syncthreads();
    if (tid < 3) {
        int u = tid;
        float m = fmaxf(E_s[u], fmaxf(E_s[3+u], E_s[6+u]));
        float e0=__expf(E_s[u]-m), e1=__expf(E_s[3+u]-m), e2=__expf(E_s[6+u]-m);
        float inv = __fdividef(1.0f, e0+e1+e2);
        At_s[u]=e0*inv; At_s[3+u]=e1*inv; At_s[6+u]=e2*inv;
    }
    __syncthreads();
    for (int i = tid; i < 930; i += NT) {
        int u = i/310, r = i%310;
        sxT[i] = (sx[r]*At_s[u] + sx[310+r]*At_s[3+u] + sx[620+r]*At_s[6+u]) * 0.056796183f;
    }
    __syncthreads();

    // ---------------- Phase 2: spatial attention ----------------
    if (tid < 186) {
        int v = tid/3, s = tid%3;
        float acc = 0.f;
        #pragma unroll
        for (int f=0; f<5; f++) {
            float yv = sxT[v*5+f]*W1_s[0] + sxT[310+v*5+f]*W1_s[1] + sxT[620+v*5+f]*W1_s[2];
            acc += yv*W2_s[f*3+s];
        }
        slhs_s[v*3+s] = acc;
    }
    if (tid < 186) {
        int t = tid/62, v = tid%62;
        const float* xr = sxT + t*310 + v*5;
        float s = 0.f;
        #pragma unroll
        for (int f=0; f<5; f++) s += W3_s[f]*xr[f];
        srhs_s[t*62+v] = s;
    }
    __syncthreads();
    for (int i = tid; i < 3844; i += NT) {   // sig(s_prod+bs) [w][v], rowstride 64
        int w = i/62, v = i%62;
        float p = slhs_s[w*3]*srhs_s[v] + slhs_s[w*3+1]*srhs_s[62+v]
                + slhs_s[w*3+2]*srhs_s[124+v] + gbs[i];
        bufSg[w*64+v] = fsig(p);
    }
    if (tid < 62) { bufSg[tid*64+62]=0.f; bufSg[tid*64+63]=0.f; }
    __syncthreads();
    {   // Sm[u][v] = sum_w Vs[u][w]*sig[w][v] ; 2u x 8v tile, 2-way w-split + shfl
        int u2 = tid>>4;
        int rem = tid&15;
        int vq = rem>>1;
        int ws = rem&1;
        int u0 = u2*2;
        bool uvalid = (u0 < 62);
        int ua = uvalid ? u0 : 0;
        float acc[16];
        #pragma unroll
        for (int k=0;k<16;k++) acc[k]=0.f;
        for (int wi=0; wi<31; wi++) {
            int w = ws*31+wi;
            float va = Vs_s[ua*62+w];
            float vb = Vs_s[(ua+1)*62+w];
            const float4* rowp = reinterpret_cast<const float4*>(bufSg + w*64 + vq*8);
            float4 s0 = rowp[0], s1 = rowp[1];
            float sv[8] = {s0.x,s0.y,s0.z,s0.w,s1.x,s1.y,s1.z,s1.w};
            #pragma unroll
            for (int j=0;j<8;j++) { acc[j] += va*sv[j]; acc[8+j] += vb*sv[j]; }
        }
        #pragma unroll
        for (int k=0;k<16;k++) acc[k] += __shfl_xor_sync(0xffffffffu, acc[k], 1);
        if (uvalid) {
            #pragma unroll
            for (int dv=0; dv<4; dv++) {
                int v = vq*8 + ws*4 + dv;
                if (v < 62) {
                    bufAt[ua*62+v]     = acc[ws*4+dv];
                    bufAt[(ua+1)*62+v] = acc[8+ws*4+dv];
                }
            }
        }
    }
    __syncthreads();
    {   // softmax over u per column v
        int v = tid>>3, g = tid&7;
        bool act = (v < 62);
        float m = -1e30f;
        if (act) for (int u=g; u<62; u+=8) m = fmaxf(m, bufAt[u*62+v]);
        #pragma unroll
        for (int o=4; o; o>>=1) m = fmaxf(m, __shfl_xor_sync(0xffffffffu, m, o));
        float ssum = 0.f;
        if (act) for (int u=g; u<62; u+=8) { float e = __expf(bufAt[u*62+v]-m); bufAt[u*62+v]=e; ssum+=e; }
        #pragma unroll
        for (int o=4; o; o>>=1) ssum += __shfl_xor_sync(0xffffffffu, ssum, o);
        float inv = __fdividef(1.0f, ssum);
        if (act) for (int u=g; u<62; u+=8) bufAt[u*62+v] *= inv;
    }
    __syncthreads();

    // ---------------- Phase 3: S matrix + losses ----------------
    const float* xm = sx + 310;
    {
        float a0=a_s[0],a1=a_s[1],a2=a_s[2],a3=a_s[3],a4=a_s[4];
        for (int i = tid; i < 3844; i += NT) {
            int ii = i/62, jj = i%62;
            const float* xi = xm + ii*5; const float* xj = xm + jj*5;
            float e = fabsf(xi[0]-xj[0])*a0 + fabsf(xi[1]-xj[1])*a1 + fabsf(xi[2]-xj[2])*a2
                    + fabsf(xi[3]-xj[3])*a3 + fabsf(xi[4]-xj[4])*a4;
            bufS[i] = __expf(fmaxf(e, 0.0f));
        }
    }
    __syncthreads();
    {
        int j = tid>>3, g = tid&7;
        bool act = (j < 62);
        float cs = 0.f;
        if (act) for (int i=g; i<62; i+=8) cs += bufS[i*62+j];
        #pragma unroll
        for (int o=4; o; o>>=1) cs += __shfl_xor_sync(0xffffffffu, cs, o);
        if (act && g==0) colsum[j] = __fdividef(1.0f, cs);
    }
    __syncthreads();
    for (int i = tid; i < 3844; i += NT) {
        float s = bufS[i] * colsum[i%62];
        bufS[i] = s;
        out[S_BASE + (size_t)b*3844 + i] = s;
    }
    __syncthreads();
    {
        int j = tid>>3, g = tid&7;
        bool act = (j < 62);
        float cs = 0.f, dd = 0.f;
        if (act) {
            const float* xj = xm + j*5;
            for (int i=g; i<62; i+=8) {
                cs += bufS[i*62+j];
                const float* xi = xm + i*5;
                #pragma unroll
                for (int f=0; f<5; f++) { float d = xj[f]-xi[f]; dd += d*d; }
            }
        }
        #pragma unroll
        for (int o=4; o; o>>=1) {
            cs += __shfl_xor_sync(0xffffffffu, cs, o);
            dd += __shfl_xor_sync(0xffffffffu, dd, o);
        }
        if (act && g==0) { DgS_s[j] = cs; d2s_s[j] = dd; }
    }
    {
        float sl = 0.f;
        for (int i = tid; i < 3844; i += NT) sl += bufS[i]*bufS[i];
        red_s[tid] = sl;
    }
    __syncthreads();
    for (int s = NT/2; s > 0; s >>= 1) {
        if (tid < s) red_s[tid] += red_s[tid+s];
        __syncthreads();
    }
    if (tid == 0) {
        atomicAdd(out + XR_ELEMS, red_s[0] * (ALPHA/(float)NBATCH));
        float dp = 0.f;
        for (int j=0; j<62; j++) dp += DgS_s[j]*d2s_s[j];
        atomicAdd(out + XR_ELEMS + 1, dp * ALPHA);
    }

    // ---------------- Phase 4a: partial cheb accumulators -> g_acc ----------------
    if (tid < 372) {
        int half = (tid >= 186);
        int r = tid - half*186;
        int t = r/62, v = r%62;
        float acc[15];
        #pragma unroll
        for (int k=0;k<15;k++) acc[k]=0.f;
        float dgm1 = DgS_s[v] - 1.0f;
        int u0 = half*31;
        for (int ui=0; ui<31; ui++) {
            int u = u0+ui;
            float s  = bufS[u*62+v];
            float at = bufAt[u*62+v];
            float delta = (u==v) ? 1.0f : 0.0f;
            float lt = dgm1*delta - s;
            float c2 = 2.0f*lt*lt - delta;
            float t0 = delta*at, t1 = lt*at, t2 = c2*at;
            const float* xr = sx + t*310 + u*5;
            #pragma unroll
            for (int f=0; f<5; f++) {
                float xv = xr[f];
                acc[f]    += t0*xv;
                acc[5+f]  += t1*xv;
                acc[10+f] += t2*xv;
            }
        }
        size_t base = (size_t)b*5580 + half*186 + t*62 + v;
        #pragma unroll
        for (int kf=0; kf<15; kf++) g_acc[base + kf*372] = acc[kf];
    }
}

// ============================ KERNEL B: phases 4b-6 ============================
__global__ void __launch_bounds__(NT,2) stgcn_b(
    const float* __restrict__ gx, const float* __restrict__ gTheta,
    const float* __restrict__ gtb, const float* __restrict__ grw,
    const float* __restrict__ grb, const float* __restrict__ ggamma,
    const float* __restrict__ gbeta, float* __restrict__ out)
{
    extern __shared__ float smarr[];
    const int tid = threadIdx.x;
    const int b = blockIdx.x;

    float* sg    = smarr;              // 12288 [t][c][v] rowstride 64
    float* zb    = sg   + 12288;       // 4032  z [v][o] rowstride 65
    float* Th_s  = zb   + 4032;        // 960   [kf][o]
    float* x0_s  = Th_s + 960;         // 320   x[b,0,:,:]
    float* tb_s  = x0_s + 320;         // 64
    float* rb_s  = tb_s + 64;          // 64
    float* rw_s  = rb_s + 64;          // 320
    float* gam_s = rw_s + 320;         // 64
    float* bet_s = gam_s+ 64;          // 64
    float* mu_s  = bet_s+ 64;          // 64
    float* iv_s  = mu_s + 64;          // 64

    for (int i = tid; i < 960; i += NT) Th_s[i] = gTheta[i];
    for (int i = tid; i < 310; i += NT) x0_s[i] = gx[(size_t)b*930 + i];
    for (int i = tid; i < 320; i += NT) rw_s[i] = grw[i];
    if (tid < 64) { tb_s[tid]=gtb[tid]; rb_s[tid]=grb[tid]; gam_s[tid]=ggamma[tid]; bet_s[tid]=gbeta[tid]; }
    __syncthreads();

    // ---------------- Phase 4b: Theta contraction -> sg ----------------
    if (tid < 372) {
        int oh = (tid >= 186);
        int r = tid - oh*186;
        int t = r/62, v = r%62;
        int tv = t*62+v;
        const float* ap = g_acc + (size_t)b*5580 + tv;
        float a0[15];
        #pragma unroll
        for (int kf=0; kf<15; kf++) a0[kf] = ap[kf*372] + ap[kf*372 + 186];
        int ob = oh*32;
        #pragma unroll 4
        for (int oi=0; oi<32; oi++) {
            int o = ob+oi;
            float z = 0.f;
            #pragma unroll
            for (int kf=0; kf<15; kf++) z += a0[kf]*Th_s[kf*64+o];
            sg[t*4096 + o*64 + v] = fmaxf(z, 0.0f);
        }
    }
    for (int i = tid; i < 192; i += NT) {   // zero sg pad cols 62,63
        int t = i/64, c = i%64;
        sg[t*4096 + c*64 + 62] = 0.f;
        sg[t*4096 + c*64 + 63] = 0.f;
    }
    __syncthreads();

    // ---------------- Phase 5: temporal conv (4o x 8v tile, 4-way c-split) ----------------
    {
        int o4  = tid>>5;           // 0..15 : warp-uniform o-group
        int rem = tid&31;
        int vq  = rem>>2;           // 0..7
        int ks  = rem&3;            // 0..3  : c-split
        int ob  = o4*4;
        float acc[32];
        #pragma unroll
        for (int k=0;k<32;k++) acc[k]=0.f;
        int c0 = ks*16;
        for (int ci=0; ci<16; ci++) {
            int c = c0+ci;
            #pragma unroll
            for (int t=0; t<3; t++) {
                const float4* rowp = reinterpret_cast<const float4*>(sg + t*4096 + c*64 + vq*8);
                float4 s0 = rowp[0], s1 = rowp[1];
                float sv[8] = {s0.x,s0.y,s0.z,s0.w,s1.x,s1.y,s1.z,s1.w};
                float4 tw4 = __ldg(reinterpret_cast<const float4*>(g_twt + ((t*64+c)<<6) + ob));
                float wv[4] = {tw4.x, tw4.y, tw4.z, tw4.w};
                #pragma unroll
                for (int oi=0; oi<4; oi++)
                    #pragma unroll
                    for (int vj=0; vj<8; vj++)
                        acc[oi*8+vj] += wv[oi]*sv[vj];
            }
        }
        #pragma unroll
        for (int k=0;k<32;k++) {
            acc[k] += __shfl_xor_sync(0xffffffffu, acc[k], 1);
            acc[k] += __shfl_xor_sync(0xffffffffu, acc[k], 2);
        }
        #pragma unroll
        for (int dv=0; dv<2; dv++) {
            int vj = ks*2+dv;
            int v = vq*8+vj;
            if (v < 62) {
                const float* x0 = x0_s + v*5;
                float xa=x0[0], xb=x0[1], xc=x0[2], xd=x0[3], xe=x0[4];
                #pragma unroll
                for (int oi=0; oi<4; oi++) {
                    int o = ob+oi;
                    float tcv = (acc[oi*8+vj] + tb_s[o]) * 0.25819889f;
                    const float* rwp = rw_s + o*5;
                    float resv = rb_s[o] + xa*rwp[0]+xb*rwp[1]+xc*rwp[2]+xd*rwp[3]+xe*rwp[4];
                    zb[v*65+o] = fmaxf(resv + tcv, 0.0f);
                }
            }
        }
    }
    __syncthreads();

    // ---------------- Phase 6: LayerNorm over H2 + writeback ----------------
    {
        int v = tid>>3, g = tid&7;
        bool act = (v < 62);
        float s = 0.f;
        if (act) for (int o=g; o<64; o+=8) s += zb[v*65+o];
        #pragma unroll
        for (int o=4; o; o>>=1) s += __shfl_xor_sync(0xffffffffu, s, o);
        float mu = s * (1.0f/64.0f);
        float vv = 0.f;
        if (act) for (int o=g; o<64; o+=8) { float d = zb[v*65+o]-mu; vv += d*d; }
        #pragma unroll
        for (int o=4; o; o>>=1) vv += __shfl_xor_sync(0xffffffffu, vv, o);
        vv *= (1.0f/64.0f);
        if (act && g==0) { mu_s[v] = mu; iv_s[v] = rsqrtf(vv + LN_EPS); }
    }
    __syncthreads();
    for (int i = tid; i < 3968; i += NT) {
        int v = i>>6, o = i&63;
        float val = (zb[v*65+o]-mu_s[v])*iv_s[v]*gam_s[o] + bet_s[o];
        out[(size_t)b*3968 + i] = val;
    }
}

#define SMEM_A_BYTES (19320*4)
#define SMEM_B_BYTES (18304*4)

extern "C" void kernel_launch(void* const* d_in, const int* in_sizes, int n_in,
                              void* d_out, int out_size) {
    const float* x     = (const float*)d_in[0];
    const float* U1    = (const float*)d_in[1];
    const float* U2    = (const float*)d_in[2];
    const float* U3    = (const float*)d_in[3];
    const float* be    = (const float*)d_in[4];
    const float* Ve    = (const float*)d_in[5];
    const float* W1    = (const float*)d_in[6];
    const float* W2    = (const float*)d_in[7];
    const float* W3    = (const float*)d_in[8];
    const float* bs    = (const float*)d_in[9];
    const float* Vs    = (const float*)d_in[10];
    const float* a     = (const float*)d_in[11];
    const float* Theta = (const float*)d_in[12];
    const float* tw    = (const float*)d_in[13];
    const float* tb    = (const float*)d_in[14];
    const float* rw    = (const float*)d_in[15];
    const float* rb    = (const float*)d_in[16];
    const float* gamma = (const float*)d_in[17];
    const float* beta  = (const float*)d_in[18];
    float* out = (float*)d_out;

    cudaFuncSetAttribute(stgcn_a, cudaFuncAttributeMaxDynamicSharedMemorySize, SMEM_A_BYTES);
    cudaFuncSetAttribute(stgcn_b, cudaFuncAttributeMaxDynamicSharedMemorySize, SMEM_B_BYTES);

    prep_kernel<<<48, 256>>>(tw, out);
    stgcn_a<<<NBATCH, NT, SMEM_A_BYTES>>>(x, U1, U2, U3, be, Ve, W1, W2, W3,
                                          bs, Vs, a, out);
    stgcn_b<<<NBATCH, NT, SMEM_B_BYTES>>>(x, Theta, tb, rw, rb, gamma, beta, out);
}

// round 5
// speedup vs baseline: 1.8884x; 1.0401x over previous
#include <cuda_runtime.h>
#include <math.h>

#define NBATCH 2048
#define ALPHA 1e-4f
#define LN_EPS 1e-5f
#define NT 512

#define XR_ELEMS (NBATCH*62*64)      /* 8126464 */
#define S_BASE   (XR_ELEMS + 2)

// Scratch: per-batch 15 x 186 cheb accumulators (full u-sum), transposed tw.
__device__ float g_acc[NBATCH*2790];     // [b][kf][t*62+v]
__device__ float g_twt[12288];           // [t][c][o]

__device__ __forceinline__ float fsig(float x){ return __fdividef(1.0f, 1.0f+__expf(-x)); }

#define HBAR(h) asm volatile("bar.sync %0, 256;" :: "r"(1+(h)) : "memory")

__global__ void prep_kernel(const float* __restrict__ gtw, float* __restrict__ out) {
    int i = blockIdx.x*256 + threadIdx.x;
    if (i < 12288) {
        int o = i/192, c = (i%192)/3, t = i%3;
        g_twt[(t*64+c)*64+o] = gtw[i];
    }
    if (i < 2) out[XR_ELEMS + i] = 0.0f;
}

// ============ KERNEL A: phases 0-4a, 2 batches per block (halves) ============
__global__ void __launch_bounds__(NT,2) stgcn_a(
    const float* __restrict__ gx, const float* __restrict__ gU1,
    const float* __restrict__ gU2, const float* __restrict__ gU3,
    const float* __restrict__ gbe, const float* __restrict__ gVe,
    const float* __restrict__ gW1, const float* __restrict__ gW2,
    const float* __restrict__ gW3, const float* __restrict__ gbs,
    const float* __restrict__ gVs, const float* __restrict__ ga,
    float* __restrict__ out)
{
    extern __shared__ float smarr[];
    const int tid = threadIdx.x;
    const int h  = tid >> 8;         // half id (0/1)
    const int lt = tid & 255;        // lane within half
    const int b  = blockIdx.x*2 + h;

    // ---- shared (read-only weights), 4288 floats ----
    float* Vs_s  = smarr;            // 3844
    float* U2_s  = Vs_s + 3844;      // 312
    float* U1_s  = U2_s + 312;       // 64
    float* U3_s  = U1_s + 64;        // 8
    float* be_s  = U3_s + 8;         // 12
    float* Ve_s  = be_s + 12;        // 12
    float* W1_s  = Ve_s + 12;        // 4
    float* W2_s  = W1_s + 4;         // 16
    float* W3_s  = W2_s + 16;        // 8
    float* a_s   = W3_s + 8;         // 8

    // ---- per-half, 10680 floats each ----
    float* hb    = smarr + 4288 + h*10680;
    float* sx    = hb;               // 932
    float* sxT   = sx   + 932;       // 932
    float* bufA  = sxT  + 932;       // 3968 : sigmoid [w][v]@64 then tmpS/S [i][j]@62
    float* bufAt = bufA + 3968;      // 3844
    float* y_s   = bufAt+ 3844;      // 16
    float* lhs_s = y_s  + 16;        // 188
    float* rhs_s = lhs_s+ 188;       // 188
    float* prod_s= rhs_s+ 188;       // 12
    float* E_s   = prod_s+12;        // 12
    float* At_s  = E_s  + 12;        // 12
    float* slhs_s= At_s + 12;        // 188
    float* srhs_s= slhs_s+188;       // 188
    float* colsum= srhs_s+188;       // 64
    float* DgS_s = colsum+ 64;       // 64
    float* d2s_s = DgS_s + 64;       // 64
    float* red_s = d2s_s + 64;       // 8

    // ---------------- stage inputs (whole block), then one full sync ----------------
    for (int i = tid; i < 3844; i += NT) Vs_s[i] = gVs[i];
    for (int i = tid; i < 310;  i += NT) U2_s[i] = gU2[i];
    if (tid < 62) U1_s[tid] = gU1[tid];
    if (tid < 5)  U3_s[tid] = gU3[tid];
    if (tid < 9)  be_s[tid] = gbe[tid];
    if (tid < 9)  Ve_s[tid] = gVe[tid];
    if (tid < 3)  W1_s[tid] = gW1[tid];
    if (tid < 15) W2_s[tid] = gW2[tid];
    if (tid < 5)  W3_s[tid] = gW3[tid];
    if (tid < 5)  a_s[tid]  = ga[tid];
    for (int i = lt; i < 930; i += 256) sx[i] = gx[(size_t)b*930 + i];
    __syncthreads();

    // ---------------- P1: y + rhs ----------------
    if (lt < 15) {
        int t = lt/5, f = lt%5;
        float s = 0.f;
        for (int v = 0; v < 62; v++) s += sx[t*310+v*5+f]*U1_s[v];
        y_s[t*5+f] = s;
    }
    if (lt >= 32 && lt < 218) {
        int r = lt-32;
        int v = r/3, t = r%3;
        const float* xr = sx + t*310 + v*5;
        float s = 0.f;
        #pragma unroll
        for (int f=0; f<5; f++) s += U3_s[f]*xr[f];
        rhs_s[v*3+t] = s;
    }
    HBAR(h);
    // ---------------- P2: lhs ----------------
    if (lt < 186) {
        int t = lt/62, u = lt%62;
        float s = 0.f;
        #pragma unroll
        for (int f=0; f<5; f++) s += y_s[t*5+f]*U2_s[f*62+u];
        lhs_s[t*62+u] = s;
    }
    HBAR(h);
    // ---------------- P3: prod ----------------
    if (lt < 9) {
        int t = lt/3, u = lt%3;
        float s = 0.f;
        for (int v=0; v<62; v++) s += lhs_s[t*62+v]*rhs_s[v*3+u];
        prod_s[t*3+u] = s;
    }
    HBAR(h);
    // ---------------- P4: E ----------------
    if (lt < 9) {
        int t = lt/3, u = lt%3;
        float s = 0.f;
        #pragma unroll
        for (int k=0; k<3; k++) s += Ve_s[t*3+k]*fsig(prod_s[k*3+u]+be_s[k*3+u]);
        E_s[t*3+u] = s;
    }
    HBAR(h);
    // ---------------- P5: softmax over t ----------------
    if (lt < 3) {
        int u = lt;
        float m = fmaxf(E_s[u], fmaxf(E_s[3+u], E_s[6+u]));
        float e0=__expf(E_s[u]-m), e1=__expf(E_s[3+u]-m), e2=__expf(E_s[6+u]-m);
        float inv = __fdividef(1.0f, e0+e1+e2);
        At_s[u]=e0*inv; At_s[3+u]=e1*inv; At_s[6+u]=e2*inv;
    }
    HBAR(h);
    // ---------------- P6: x_TAt ----------------
    for (int i = lt; i < 930; i += 256) {
        int u = i/310, r = i%310;
        sxT[i] = (sx[r]*At_s[u] + sx[310+r]*At_s[3+u] + sx[620+r]*At_s[6+u]) * 0.056796183f;
    }
    HBAR(h);
    // ---------------- P7: slhs + srhs ----------------
    if (lt < 186) {
        int v = lt/3, s = lt%3;
        float acc = 0.f;
        #pragma unroll
        for (int f=0; f<5; f++) {
            float yv = sxT[v*5+f]*W1_s[0] + sxT[310+v*5+f]*W1_s[1] + sxT[620+v*5+f]*W1_s[2];
            acc += yv*W2_s[f*3+s];
        }
        slhs_s[v*3+s] = acc;
        int t = lt/62, vv = lt%62;
        const float* xr = sxT + t*310 + vv*5;
        float s2 = 0.f;
        #pragma unroll
        for (int f=0; f<5; f++) s2 += W3_s[f]*xr[f];
        srhs_s[t*62+vv] = s2;
    }
    HBAR(h);
    // ---------------- P8: sigmoid map [w][v] stride 64 ----------------
    for (int i = lt; i < 3844; i += 256) {
        int w = i/62, v = i%62;
        float p = slhs_s[w*3]*srhs_s[v] + slhs_s[w*3+1]*srhs_s[62+v]
                + slhs_s[w*3+2]*srhs_s[124+v] + gbs[i];
        bufA[w*64+v] = fsig(p);
    }
    if (lt < 62) { bufA[lt*64+62]=0.f; bufA[lt*64+63]=0.f; }
    HBAR(h);
    // ---------------- P9: Sm matmul (2u x 8v tile) ----------------
    {
        int u2 = lt>>3;             // 0..31
        int vq = lt&7;              // 0..7
        int u0 = u2*2;
        if (u0 < 62) {
            float acc[16];
            #pragma unroll
            for (int k=0;k<16;k++) acc[k]=0.f;
            for (int w=0; w<62; w++) {
                float va = Vs_s[u0*62+w];
                float vb = Vs_s[(u0+1)*62+w];
                const float4* rowp = reinterpret_cast<const float4*>(bufA + w*64 + vq*8);
                float4 s0 = rowp[0], s1 = rowp[1];
                float sv[8] = {s0.x,s0.y,s0.z,s0.w,s1.x,s1.y,s1.z,s1.w};
                #pragma unroll
                for (int j=0;j<8;j++) { acc[j] += va*sv[j]; acc[8+j] += vb*sv[j]; }
            }
            #pragma unroll
            for (int j=0;j<8;j++) {
                int v = vq*8+j;
                if (v < 62) {
                    bufAt[u0*62+v]     = acc[j];
                    bufAt[(u0+1)*62+v] = acc[8+j];
                }
            }
        }
    }
    HBAR(h);
    // ---------------- P10: softmax over u per column v (4 lanes/col) ----------------
    {
        int v = lt>>2, g = lt&3;
        bool act = (v < 62);
        float m = -1e30f;
        if (act) for (int u=g; u<62; u+=4) m = fmaxf(m, bufAt[u*62+v]);
        m = fmaxf(m, __shfl_xor_sync(0xffffffffu, m, 1));
        m = fmaxf(m, __shfl_xor_sync(0xffffffffu, m, 2));
        float ssum = 0.f;
        if (act) for (int u=g; u<62; u+=4) { float e = __expf(bufAt[u*62+v]-m); bufAt[u*62+v]=e; ssum+=e; }
        ssum += __shfl_xor_sync(0xffffffffu, ssum, 1);
        ssum += __shfl_xor_sync(0xffffffffu, ssum, 2);
        float inv = __fdividef(1.0f, ssum);
        if (act) for (int u=g; u<62; u+=4) bufAt[u*62+v] *= inv;
    }
    HBAR(h);
    // ---------------- P11: tmpS (reuse bufA, stride 62) ----------------
    const float* xm = sx + 310;
    {
        float a0=a_s[0],a1=a_s[1],a2=a_s[2],a3=a_s[3],a4=a_s[4];
        for (int i = lt; i < 3844; i += 256) {
            int ii = i/62, jj = i%62;
            const float* xi = xm + ii*5; const float* xj = xm + jj*5;
            float e = fabsf(xi[0]-xj[0])*a0 + fabsf(xi[1]-xj[1])*a1 + fabsf(xi[2]-xj[2])*a2
                    + fabsf(xi[3]-xj[3])*a3 + fabsf(xi[4]-xj[4])*a4;
            bufA[i] = __expf(fmaxf(e, 0.0f));
        }
    }
    HBAR(h);
    // ---------------- P12: column reciprocal ----------------
    {
        int j = lt>>2, g = lt&3;
        bool act = (j < 62);
        float cs = 0.f;
        if (act) for (int i=g; i<62; i+=4) cs += bufA[i*62+j];
        cs += __shfl_xor_sync(0xffffffffu, cs, 1);
        cs += __shfl_xor_sync(0xffffffffu, cs, 2);
        if (act && g==0) colsum[j] = __fdividef(1.0f, cs);
    }
    HBAR(h);
    // ---------------- P13: normalize + store S ----------------
    for (int i = lt; i < 3844; i += 256) {
        float s = bufA[i] * colsum[i%62];
        bufA[i] = s;
        out[S_BASE + (size_t)b*3844 + i] = s;
    }
    HBAR(h);
    // ---------------- P14: Dg + d2 ----------------
    {
        int j = lt>>2, g = lt&3;
        bool act = (j < 62);
        float cs = 0.f, dd = 0.f;
        if (act) {
            const float* xj = xm + j*5;
            for (int i=g; i<62; i+=4) {
                cs += bufA[i*62+j];
                const float* xi = xm + i*5;
                #pragma unroll
                for (int f=0; f<5; f++) { float d = xj[f]-xi[f]; dd += d*d; }
            }
        }
        cs += __shfl_xor_sync(0xffffffffu, cs, 1);
        cs += __shfl_xor_sync(0xffffffffu, cs, 2);
        dd += __shfl_xor_sync(0xffffffffu, dd, 1);
        dd += __shfl_xor_sync(0xffffffffu, dd, 2);
        if (act && g==0) { DgS_s[j] = cs; d2s_s[j] = dd; }
    }
    HBAR(h);
    // ---------------- P15: Sloss partials (warp-reduced) ----------------
    {
        float sl = 0.f;
        for (int i = lt; i < 3844; i += 256) sl += bufA[i]*bufA[i];
        #pragma unroll
        for (int o=16; o; o>>=1) sl += __shfl_xor_sync(0xffffffffu, sl, o);
        if ((lt&31)==0) red_s[lt>>5] = sl;
    }
    HBAR(h);
    // ---------------- P16: cheb accumulators (full u) + loss finalize ----------------
    if (lt < 186) {
        int t = lt/62, v = lt%62;
        float acc[15];
        #pragma unroll
        for (int k=0;k<15;k++) acc[k]=0.f;
        float dgm1 = DgS_s[v] - 1.0f;
        for (int u=0; u<62; u++) {
            float s  = bufA[u*62+v];
            float at = bufAt[u*62+v];
            float delta = (u==v) ? 1.0f : 0.0f;
            float lt_ = dgm1*delta - s;
            float c2 = 2.0f*lt_*lt_ - delta;
            float t0 = delta*at, t1 = lt_*at, t2 = c2*at;
            const float* xr = sx + t*310 + u*5;
            #pragma unroll
            for (int f=0; f<5; f++) {
                float xv = xr[f];
                acc[f]    += t0*xv;
                acc[5+f]  += t1*xv;
                acc[10+f] += t2*xv;
            }
        }
        size_t base = (size_t)b*2790 + t*62 + v;
        #pragma unroll
        for (int kf=0; kf<15; kf++) g_acc[base + kf*186] = acc[kf];
    } else if (lt == 192) {
        float sl = 0.f;
        #pragma unroll
        for (int w=0; w<8; w++) sl += red_s[w];
        atomicAdd(out + XR_ELEMS, sl * (ALPHA/(float)NBATCH));
        float dp = 0.f;
        for (int j=0; j<62; j++) dp += DgS_s[j]*d2s_s[j];
        atomicAdd(out + XR_ELEMS + 1, dp * ALPHA);
    }
}

// ============================ KERNEL B: phases 4b-6 ============================
__global__ void __launch_bounds__(NT,2) stgcn_b(
    const float* __restrict__ gx, const float* __restrict__ gTheta,
    const float* __restrict__ gtb, const float* __restrict__ grw,
    const float* __restrict__ grb, const float* __restrict__ ggamma,
    const float* __restrict__ gbeta, float* __restrict__ out)
{
    extern __shared__ float smarr[];
    const int tid = threadIdx.x;
    const int b = blockIdx.x;

    float* sg    = smarr;              // 12288 [t][c][v] rowstride 64
    float* zb    = sg   + 12288;       // 4032  z [v][o] rowstride 65
    float* Th_s  = zb   + 4032;        // 960   [kf][o]
    float* x0_s  = Th_s + 960;         // 320
    float* tb_s  = x0_s + 320;         // 64
    float* rb_s  = tb_s + 64;          // 64
    float* rw_s  = rb_s + 64;          // 320
    float* gam_s = rw_s + 320;         // 64
    float* bet_s = gam_s+ 64;          // 64
    float* mu_s  = bet_s+ 64;          // 64
    float* iv_s  = mu_s + 64;          // 64

    for (int i = tid; i < 960; i += NT) Th_s[i] = gTheta[i];
    for (int i = tid; i < 310; i += NT) x0_s[i] = gx[(size_t)b*930 + i];
    for (int i = tid; i < 320; i += NT) rw_s[i] = grw[i];
    if (tid < 64) { tb_s[tid]=gtb[tid]; rb_s[tid]=grb[tid]; gam_s[tid]=ggamma[tid]; bet_s[tid]=gbeta[tid]; }
    __syncthreads();

    // ---------------- Phase 4b: Theta contraction -> sg ----------------
    if (tid < 372) {
        int oh = (tid >= 186);
        int r = tid - oh*186;
        int t = r/62, v = r%62;
        int tv = t*62+v;
        const float* ap = g_acc + (size_t)b*2790 + tv;
        float a0[15];
        #pragma unroll
        for (int kf=0; kf<15; kf++) a0[kf] = __ldg(ap + kf*186);
        int ob = oh*32;
        #pragma unroll 4
        for (int oi=0; oi<32; oi++) {
            int o = ob+oi;
            float z = 0.f;
            #pragma unroll
            for (int kf=0; kf<15; kf++) z += a0[kf]*Th_s[kf*64+o];
            sg[t*4096 + o*64 + v] = fmaxf(z, 0.0f);
        }
    }
    for (int i = tid; i < 192; i += NT) {
        int t = i/64, c = i%64;
        sg[t*4096 + c*64 + 62] = 0.f;
        sg[t*4096 + c*64 + 63] = 0.f;
    }
    __syncthreads();

    // ---------------- Phase 5: temporal conv (4o x 8v, 4-way c-split) ----------------
    {
        int o4  = tid>>5;
        int rem = tid&31;
        int vq  = rem>>2;
        int ks  = rem&3;
        int ob  = o4*4;
        float acc[32];
        #pragma unroll
        for (int k=0;k<32;k++) acc[k]=0.f;
        int c0 = ks*16;
        for (int ci=0; ci<16; ci++) {
            int c = c0+ci;
            #pragma unroll
            for (int t=0; t<3; t++) {
                const float4* rowp = reinterpret_cast<const float4*>(sg + t*4096 + c*64 + vq*8);
                float4 s0 = rowp[0], s1 = rowp[1];
                float sv[8] = {s0.x,s0.y,s0.z,s0.w,s1.x,s1.y,s1.z,s1.w};
                float4 tw4 = __ldg(reinterpret_cast<const float4*>(g_twt + ((t*64+c)<<6) + ob));
                float wv[4] = {tw4.x, tw4.y, tw4.z, tw4.w};
                #pragma unroll
                for (int oi=0; oi<4; oi++)
                    #pragma unroll
                    for (int vj=0; vj<8; vj++)
                        acc[oi*8+vj] += wv[oi]*sv[vj];
            }
        }
        #pragma unroll
        for (int k=0;k<32;k++) {
            acc[k] += __shfl_xor_sync(0xffffffffu, acc[k], 1);
            acc[k] += __shfl_xor_sync(0xffffffffu, acc[k], 2);
        }
        #pragma unroll
        for (int dv=0; dv<2; dv++) {
            int vj = ks*2+dv;
            int v = vq*8+vj;
            if (v < 62) {
                const float* x0 = x0_s + v*5;
                float xa=x0[0], xb=x0[1], xc=x0[2], xd=x0[3], xe=x0[4];
                #pragma unroll
                for (int oi=0; oi<4; oi++) {
                    int o = ob+oi;
                    float tcv = (acc[oi*8+vj] + tb_s[o]) * 0.25819889f;
                    const float* rwp = rw_s + o*5;
                    float resv = rb_s[o] + xa*rwp[0]+xb*rwp[1]+xc*rwp[2]+xd*rwp[3]+xe*rwp[4];
                    zb[v*65+o] = fmaxf(resv + tcv, 0.0f);
                }
            }
        }
    }
    __syncthreads();

    // ---------------- Phase 6: LayerNorm + writeback ----------------
    {
        int v = tid>>3, g = tid&7;
        bool act = (v < 62);
        float s = 0.f;
        if (act) for (int o=g; o<64; o+=8) s += zb[v*65+o];
        #pragma unroll
        for (int o=4; o; o>>=1) s += __shfl_xor_sync(0xffffffffu, s, o);
        float mu = s * (1.0f/64.0f);
        float vv = 0.f;
        if (act) for (int o=g; o<64; o+=8) { float d = zb[v*65+o]-mu; vv += d*d; }
        #pragma unroll
        for (int o=4; o; o>>=1) vv += __shfl_xor_sync(0xffffffffu, vv, o);
        vv *= (1.0f/64.0f);
        if (act && g==0) { mu_s[v] = mu; iv_s[v] = rsqrtf(vv + LN_EPS); }
    }
    __syncthreads();
    for (int i = tid; i < 3968; i += NT) {
        int v = i>>6, o = i&63;
        float val = (zb[v*65+o]-mu_s[v])*iv_s[v]*gam_s[o] + bet_s[o];
        out[(size_t)b*3968 + i] = val;
    }
}

#define SMEM_A_BYTES (25648*4)
#define SMEM_B_BYTES (18304*4)

extern "C" void kernel_launch(void* const* d_in, const int* in_sizes, int n_in,
                              void* d_out, int out_size) {
    const float* x     = (const float*)d_in[0];
    const float* U1    = (const float*)d_in[1];
    const float* U2    = (const float*)d_in[2];
    const float* U3    = (const float*)d_in[3];
    const float* be    = (const float*)d_in[4];
    const float* Ve    = (const float*)d_in[5];
    const float* W1    = (const float*)d_in[6];
    const float* W2    = (const float*)d_in[7];
    const float* W3    = (const float*)d_in[8];
    const float* bs    = (const float*)d_in[9];
    const float* Vs    = (const float*)d_in[10];
    const float* a     = (const float*)d_in[11];
    const float* Theta = (const float*)d_in[12];
    const float* tw    = (const float*)d_in[13];
    const float* tb    = (const float*)d_in[14];
    const float* rw    = (const float*)d_in[15];
    const float* rb    = (const float*)d_in[16];
    const float* gamma = (const float*)d_in[17];
    const float* beta  = (const float*)d_in[18];
    float* out = (float*)d_out;

    cudaFuncSetAttribute(stgcn_a, cudaFuncAttributeMaxDynamicSharedMemorySize, SMEM_A_BYTES);
    cudaFuncSetAttribute(stgcn_b, cudaFuncAttributeMaxDynamicSharedMemorySize, SMEM_B_BYTES);

    prep_kernel<<<48, 256>>>(tw, out);
    stgcn_a<<<NBATCH/2, NT, SMEM_A_BYTES>>>(x, U1, U2, U3, be, Ve, W1, W2, W3,
                                            bs, Vs, a, out);
    stgcn_b<<<NBATCH, NT, SMEM_B_BYTES>>>(x, Theta, tb, rw, rb, gamma, beta, out);
}

// round 6
// speedup vs baseline: 2.1813x; 1.1551x over previous
#include <cuda_runtime.h>
#include <math.h>

#define NBATCH 2048
#define ALPHA 1e-4f
#define LN_EPS 1e-5f

#define XR_ELEMS (NBATCH*62*64)      /* 8126464 */
#define S_BASE   (XR_ELEMS + 2)

// Scratch: per-batch 15 x 186 cheb accumulators (full u-sum), transposed tw.
__device__ float g_acc[NBATCH*2790];     // [b][kf][t*62+v]
__device__ float g_twt[12288];           // [t][c][o]

__device__ __forceinline__ float fsig(float x){ return __fdividef(1.0f, 1.0f+__expf(-x)); }

__global__ void prep_kernel(const float* __restrict__ gtw, float* __restrict__ out) {
    int i = blockIdx.x*256 + threadIdx.x;
    if (i < 12288) {
        int o = i/192, c = (i%192)/3, t = i%3;
        g_twt[(t*64+c)*64+o] = gtw[i];
    }
    if (i < 2) out[XR_ELEMS + i] = 0.0f;
}

// ============ KERNEL A: phases 0-4a, 256 threads, 1 batch/block ============
__global__ void __launch_bounds__(256,5) stgcn_a(
    const float* __restrict__ gx, const float* __restrict__ gU1,
    const float* __restrict__ gU2, const float* __restrict__ gU3,
    const float* __restrict__ gbe, const float* __restrict__ gVe,
    const float* __restrict__ gW1, const float* __restrict__ gW2,
    const float* __restrict__ gW3, const float* __restrict__ gbs,
    const float* __restrict__ gVs, const float* __restrict__ ga,
    float* __restrict__ out)
{
    extern __shared__ float smarr[];
    const int lt = threadIdx.x;
    const int b  = blockIdx.x;

    float* sx    = smarr;            // 932
    float* sxT   = sx   + 932;       // 932
    float* bufA  = sxT  + 932;       // 3968 : sigmoid [w][v]@64 then tmpS/S [i][j]@62
    float* bufAt = bufA + 3968;      // 3844
    float* y_s   = bufAt+ 3844;      // 16
    float* lhs_s = y_s  + 16;        // 188
    float* rhs_s = lhs_s+ 188;       // 188
    float* prod_s= rhs_s+ 188;       // 12
    float* E_s   = prod_s+12;        // 12
    float* At_s  = E_s  + 12;        // 12
    float* slhs_s= At_s + 12;        // 188
    float* srhs_s= slhs_s+188;       // 188
    float* colsum= srhs_s+188;       // 64
    float* DgS_s = colsum+ 64;       // 64
    float* d2s_s = DgS_s + 64;       // 64
    float* red_s = d2s_s + 64;       // 8
    float* U2_s  = red_s + 8;        // 312
    float* U1_s  = U2_s + 312;       // 64
    float* U3_s  = U1_s + 64;        // 8
    float* be_s  = U3_s + 8;         // 12
    float* Ve_s  = be_s + 12;        // 12
    float* W1_s  = Ve_s + 12;        // 4
    float* W2_s  = W1_s + 4;         // 16
    float* W3_s  = W2_s + 16;        // 8
    float* a_s   = W3_s + 8;         // 8

    // ---------------- stage ----------------
    for (int i = lt; i < 930; i += 256) sx[i] = gx[(size_t)b*930 + i];
    if (lt >= 128 && lt < 128+155) {   // U2: 310 in 2 per thread
        U2_s[(lt-128)*2]   = gU2[(lt-128)*2];
        U2_s[(lt-128)*2+1] = gU2[(lt-128)*2+1];
    }
    if (lt < 62) U1_s[lt] = gU1[lt];
    else if (lt >= 64 && lt < 69)  U3_s[lt-64] = gU3[lt-64];
    else if (lt >= 70 && lt < 79)  be_s[lt-70] = gbe[lt-70];
    else if (lt >= 80 && lt < 89)  Ve_s[lt-80] = gVe[lt-80];
    else if (lt >= 90 && lt < 93)  W1_s[lt-90] = gW1[lt-90];
    else if (lt >= 96 && lt < 111) W2_s[lt-96] = gW2[lt-96];
    else if (lt >= 112 && lt < 117) W3_s[lt-112] = gW3[lt-112];
    else if (lt >= 118 && lt < 123) a_s[lt-118] = ga[lt-118];
    __syncthreads();

    // ---------------- P1: y + rhs ----------------
    if (lt < 15) {
        int t = lt/5, f = lt%5;
        float s = 0.f;
        for (int v = 0; v < 62; v++) s += sx[t*310+v*5+f]*U1_s[v];
        y_s[t*5+f] = s;
    }
    if (lt >= 32 && lt < 218) {
        int r = lt-32;
        int v = r/3, t = r%3;
        const float* xr = sx + t*310 + v*5;
        float s = 0.f;
        #pragma unroll
        for (int f=0; f<5; f++) s += U3_s[f]*xr[f];
        rhs_s[v*3+t] = s;
    }
    __syncthreads();
    // ---------------- P2: lhs ----------------
    if (lt < 186) {
        int t = lt/62, u = lt%62;
        float s = 0.f;
        #pragma unroll
        for (int f=0; f<5; f++) s += y_s[t*5+f]*U2_s[f*62+u];
        lhs_s[t*62+u] = s;
    }
    __syncthreads();
    // ---------------- P3: prod ----------------
    if (lt < 9) {
        int t = lt/3, u = lt%3;
        float s = 0.f;
        for (int v=0; v<62; v++) s += lhs_s[t*62+v]*rhs_s[v*3+u];
        prod_s[t*3+u] = s;
    }
    __syncthreads();
    // ---------------- P4: E ----------------
    if (lt < 9) {
        int t = lt/3, u = lt%3;
        float s = 0.f;
        #pragma unroll
        for (int k=0; k<3; k++) s += Ve_s[t*3+k]*fsig(prod_s[k*3+u]+be_s[k*3+u]);
        E_s[t*3+u] = s;
    }
    __syncthreads();
    // ---------------- P5: softmax over t ----------------
    if (lt < 3) {
        int u = lt;
        float m = fmaxf(E_s[u], fmaxf(E_s[3+u], E_s[6+u]));
        float e0=__expf(E_s[u]-m), e1=__expf(E_s[3+u]-m), e2=__expf(E_s[6+u]-m);
        float inv = __fdividef(1.0f, e0+e1+e2);
        At_s[u]=e0*inv; At_s[3+u]=e1*inv; At_s[6+u]=e2*inv;
    }
    __syncthreads();
    // ---------------- P6: x_TAt ----------------
    for (int i = lt; i < 930; i += 256) {
        int u = i/310, r = i%310;
        sxT[i] = (sx[r]*At_s[u] + sx[310+r]*At_s[3+u] + sx[620+r]*At_s[6+u]) * 0.056796183f;
    }
    __syncthreads();
    // ---------------- P7: slhs + srhs ----------------
    if (lt < 186) {
        int v = lt/3, s = lt%3;
        float acc = 0.f;
        #pragma unroll
        for (int f=0; f<5; f++) {
            float yv = sxT[v*5+f]*W1_s[0] + sxT[310+v*5+f]*W1_s[1] + sxT[620+v*5+f]*W1_s[2];
            acc += yv*W2_s[f*3+s];
        }
        slhs_s[v*3+s] = acc;
        int t = lt/62, vv = lt%62;
        const float* xr = sxT + t*310 + vv*5;
        float s2 = 0.f;
        #pragma unroll
        for (int f=0; f<5; f++) s2 += W3_s[f]*xr[f];
        srhs_s[t*62+vv] = s2;
    }
    __syncthreads();
    // ---------------- P8: sigmoid map [w][v] stride 64 ----------------
    for (int i = lt; i < 3844; i += 256) {
        int w = i/62, v = i%62;
        float p = slhs_s[w*3]*srhs_s[v] + slhs_s[w*3+1]*srhs_s[62+v]
                + slhs_s[w*3+2]*srhs_s[124+v] + gbs[i];
        bufA[w*64+v] = fsig(p);
    }
    if (lt < 62) { bufA[lt*64+62]=0.f; bufA[lt*64+63]=0.f; }
    __syncthreads();
    // ---------------- P9: Sm matmul (2u x 8v tile), Vs from L1/global ----------------
    {
        int u2 = lt>>3;             // 0..31
        int vq = lt&7;              // 0..7
        int u0 = u2*2;
        if (u0 < 62) {
            float acc[16];
            #pragma unroll
            for (int k=0;k<16;k++) acc[k]=0.f;
            const float* va_p = gVs + u0*62;
            const float* vb_p = va_p + 62;
            for (int w=0; w<62; w++) {
                float va = __ldg(va_p + w);
                float vb = __ldg(vb_p + w);
                const float4* rowp = reinterpret_cast<const float4*>(bufA + w*64 + vq*8);
                float4 s0 = rowp[0], s1 = rowp[1];
                float sv[8] = {s0.x,s0.y,s0.z,s0.w,s1.x,s1.y,s1.z,s1.w};
                #pragma unroll
                for (int j=0;j<8;j++) { acc[j] += va*sv[j]; acc[8+j] += vb*sv[j]; }
            }
            #pragma unroll
            for (int j=0;j<8;j++) {
                int v = vq*8+j;
                if (v < 62) {
                    bufAt[u0*62+v]     = acc[j];
                    bufAt[(u0+1)*62+v] = acc[8+j];
                }
            }
        }
    }
    __syncthreads();
    // ---------------- P10: softmax over u per column v (4 lanes/col) ----------------
    {
        int v = lt>>2, g = lt&3;
        bool act = (v < 62);
        float m = -1e30f;
        if (act) for (int u=g; u<62; u+=4) m = fmaxf(m, bufAt[u*62+v]);
        m = fmaxf(m, __shfl_xor_sync(0xffffffffu, m, 1));
        m = fmaxf(m, __shfl_xor_sync(0xffffffffu, m, 2));
        float ssum = 0.f;
        if (act) for (int u=g; u<62; u+=4) { float e = __expf(bufAt[u*62+v]-m); bufAt[u*62+v]=e; ssum+=e; }
        ssum += __shfl_xor_sync(0xffffffffu, ssum, 1);
        ssum += __shfl_xor_sync(0xffffffffu, ssum, 2);
        float inv = __fdividef(1.0f, ssum);
        if (act) for (int u=g; u<62; u+=4) bufAt[u*62+v] *= inv;
    }
    __syncthreads();
    // ---------------- P11: tmpS (reuse bufA, stride 62) ----------------
    const float* xm = sx + 310;
    {
        float a0=a_s[0],a1=a_s[1],a2=a_s[2],a3=a_s[3],a4=a_s[4];
        for (int i = lt; i < 3844; i += 256) {
            int ii = i/62, jj = i%62;
            const float* xi = xm + ii*5; const float* xj = xm + jj*5;
            float e = fabsf(xi[0]-xj[0])*a0 + fabsf(xi[1]-xj[1])*a1 + fabsf(xi[2]-xj[2])*a2
                    + fabsf(xi[3]-xj[3])*a3 + fabsf(xi[4]-xj[4])*a4;
            bufA[i] = __expf(fmaxf(e, 0.0f));
        }
    }
    __syncthreads();
    // ---------------- P12: column reciprocal ----------------
    {
        int j = lt>>2, g = lt&3;
        bool act = (j < 62);
        float cs = 0.f;
        if (act) for (int i=g; i<62; i+=4) cs += bufA[i*62+j];
        cs += __shfl_xor_sync(0xffffffffu, cs, 1);
        cs += __shfl_xor_sync(0xffffffffu, cs, 2);
        if (act && g==0) colsum[j] = __fdividef(1.0f, cs);
    }
    __syncthreads();
    // ---------------- P13: normalize + store S ----------------
    for (int i = lt; i < 3844; i += 256) {
        float s = bufA[i] * colsum[i%62];
        bufA[i] = s;
        out[S_BASE + (size_t)b*3844 + i] = s;
    }
    __syncthreads();
    // ---------------- P14: Dg + d2 ----------------
    {
        int j = lt>>2, g = lt&3;
        bool act = (j < 62);
        float cs = 0.f, dd = 0.f;
        if (act) {
            const float* xj = xm + j*5;
            for (int i=g; i<62; i+=4) {
                cs += bufA[i*62+j];
                const float* xi = xm + i*5;
                #pragma unroll
                for (int f=0; f<5; f++) { float d = xj[f]-xi[f]; dd += d*d; }
            }
        }
        cs += __shfl_xor_sync(0xffffffffu, cs, 1);
        cs += __shfl_xor_sync(0xffffffffu, cs, 2);
        dd += __shfl_xor_sync(0xffffffffu, dd, 1);
        dd += __shfl_xor_sync(0xffffffffu, dd, 2);
        if (act && g==0) { DgS_s[j] = cs; d2s_s[j] = dd; }
    }
    __syncthreads();
    // ---------------- P15: Sloss partials ----------------
    {
        float sl = 0.f;
        for (int i = lt; i < 3844; i += 256) sl += bufA[i]*bufA[i];
        #pragma unroll
        for (int o=16; o; o>>=1) sl += __shfl_xor_sync(0xffffffffu, sl, o);
        if ((lt&31)==0) red_s[lt>>5] = sl;
    }
    __syncthreads();
    // ---------------- P16: cheb accumulators + loss finalize ----------------
    if (lt < 186) {
        int t = lt/62, v = lt%62;
        float acc[15];
        #pragma unroll
        for (int k=0;k<15;k++) acc[k]=0.f;
        float dgm1 = DgS_s[v] - 1.0f;
        for (int u=0; u<62; u++) {
            float s  = bufA[u*62+v];
            float at = bufAt[u*62+v];
            float delta = (u==v) ? 1.0f : 0.0f;
            float lt_ = dgm1*delta - s;
            float c2 = 2.0f*lt_*lt_ - delta;
            float t0 = delta*at, t1 = lt_*at, t2 = c2*at;
            const float* xr = sx + t*310 + u*5;
            #pragma unroll
            for (int f=0; f<5; f++) {
                float xv = xr[f];
                acc[f]    += t0*xv;
                acc[5+f]  += t1*xv;
                acc[10+f] += t2*xv;
            }
        }
        size_t base = (size_t)b*2790 + t*62 + v;
        #pragma unroll
        for (int kf=0; kf<15; kf++) g_acc[base + kf*186] = acc[kf];
    } else if (lt == 192) {
        float sl = 0.f;
        #pragma unroll
        for (int w=0; w<8; w++) sl += red_s[w];
        atomicAdd(out + XR_ELEMS, sl * (ALPHA/(float)NBATCH));
        float dp = 0.f;
        for (int j=0; j<62; j++) dp += DgS_s[j]*d2s_s[j];
        atomicAdd(out + XR_ELEMS + 1, dp * ALPHA);
    }
}

// ============================ KERNEL B: phases 4b-6 ============================
__global__ void __launch_bounds__(512,3) stgcn_b(
    const float* __restrict__ gx, const float* __restrict__ gTheta,
    const float* __restrict__ gtb, const float* __restrict__ grw,
    const float* __restrict__ grb, const float* __restrict__ ggamma,
    const float* __restrict__ gbeta, float* __restrict__ out)
{
    extern __shared__ float smarr[];
    const int tid = threadIdx.x;
    const int b = blockIdx.x;

    float* sg    = smarr;              // 12288 [t][c][v] rowstride 64
    float* zb    = sg   + 12288;       // 4032  z [v][o] rowstride 65
    float* Th_s  = zb   + 4032;        // 960   [kf][o]
    float* x0_s  = Th_s + 960;         // 320
    float* tb_s  = x0_s + 320;         // 64
    float* rb_s  = tb_s + 64;          // 64
    float* rw_s  = rb_s + 64;          // 320
    float* gam_s = rw_s + 320;         // 64
    float* bet_s = gam_s+ 64;          // 64
    float* mu_s  = bet_s+ 64;          // 64
    float* iv_s  = mu_s + 64;          // 64

    for (int i = tid; i < 960; i += 512) Th_s[i] = gTheta[i];
    for (int i = tid; i < 310; i += 512) x0_s[i] = gx[(size_t)b*930 + i];
    for (int i = tid; i < 320; i += 512) rw_s[i] = grw[i];
    if (tid < 64) { tb_s[tid]=gtb[tid]; rb_s[tid]=grb[tid]; gam_s[tid]=ggamma[tid]; bet_s[tid]=gbeta[tid]; }
    __syncthreads();

    // ---------------- Phase 4b: Theta contraction -> sg ----------------
    if (tid < 372) {
        int oh = (tid >= 186);
        int r = tid - oh*186;
        int t = r/62, v = r%62;
        int tv = t*62+v;
        const float* ap = g_acc + (size_t)b*2790 + tv;
        float a0[15];
        #pragma unroll
        for (int kf=0; kf<15; kf++) a0[kf] = __ldg(ap + kf*186);
        int ob = oh*32;
        #pragma unroll 4
        for (int oi=0; oi<32; oi++) {
            int o = ob+oi;
            float z = 0.f;
            #pragma unroll
            for (int kf=0; kf<15; kf++) z += a0[kf]*Th_s[kf*64+o];
            sg[t*4096 + o*64 + v] = fmaxf(z, 0.0f);
        }
    }
    for (int i = tid; i < 192; i += 512) {
        int t = i/64, c = i%64;
        sg[t*4096 + c*64 + 62] = 0.f;
        sg[t*4096 + c*64 + 63] = 0.f;
    }
    __syncthreads();

    // ---------------- Phase 5: temporal conv (2o x 8v, 2-way c-split) ----------------
    {
        int o2  = tid>>4;           // 0..31 -> o0 = o2*2
        int rem = tid&15;
        int vq  = rem>>1;           // 0..7
        int ks  = rem&1;            // c-split: ks*32 .. +32
        int o0  = o2*2;
        float acc[16];              // [oi*8+vj]
        #pragma unroll
        for (int k=0;k<16;k++) acc[k]=0.f;
        int c0 = ks*32;
        for (int ci=0; ci<32; ci++) {
            int c = c0+ci;
            #pragma unroll
            for (int t=0; t<3; t++) {
                const float4* rowp = reinterpret_cast<const float4*>(sg + t*4096 + c*64 + vq*8);
                float4 s0 = rowp[0], s1 = rowp[1];
                float2 tw2 = __ldg(reinterpret_cast<const float2*>(g_twt + ((t*64+c)<<6) + o0));
                float sv[8] = {s0.x,s0.y,s0.z,s0.w,s1.x,s1.y,s1.z,s1.w};
                #pragma unroll
                for (int vj=0; vj<8; vj++) {
                    acc[vj]   += tw2.x*sv[vj];
                    acc[8+vj] += tw2.y*sv[vj];
                }
            }
        }
        #pragma unroll
        for (int k=0;k<16;k++) acc[k] += __shfl_xor_sync(0xffffffffu, acc[k], 1);
        // lane ks writes vj in [ks*4, ks*4+4)
        #pragma unroll
        for (int dv=0; dv<4; dv++) {
            int vj = ks*4+dv;
            int v = vq*8+vj;
            if (v < 62) {
                const float* x0 = x0_s + v*5;
                float xa=x0[0], xb=x0[1], xc=x0[2], xd=x0[3], xe=x0[4];
                #pragma unroll
                for (int oi=0; oi<2; oi++) {
                    int o = o0+oi;
                    float tcv = (acc[oi*8+vj] + tb_s[o]) * 0.25819889f;
                    const float* rwp = rw_s + o*5;
                    float resv = rb_s[o] + xa*rwp[0]+xb*rwp[1]+xc*rwp[2]+xd*rwp[3]+xe*rwp[4];
                    zb[v*65+o] = fmaxf(resv + tcv, 0.0f);
                }
            }
        }
    }
    __syncthreads();

    // ---------------- Phase 6: LayerNorm + writeback ----------------
    {
        int v = tid>>3, g = tid&7;
        bool act = (v < 62);
        float s = 0.f;
        if (act) for (int o=g; o<64; o+=8) s += zb[v*65+o];
        #pragma unroll
        for (int o=4; o; o>>=1) s += __shfl_xor_sync(0xffffffffu, s, o);
        float mu = s * (1.0f/64.0f);
        float vv = 0.f;
        if (act) for (int o=g; o<64; o+=8) { float d = zb[v*65+o]-mu; vv += d*d; }
        #pragma unroll
        for (int o=4; o; o>>=1) vv += __shfl_xor_sync(0xffffffffu, vv, o);
        vv *= (1.0f/64.0f);
        if (act && g==0) { mu_s[v] = mu; iv_s[v] = rsqrtf(vv + LN_EPS); }
    }
    __syncthreads();
    for (int i = tid; i < 3968; i += 512) {
        int v = i>>6, o = i&63;
        float val = (zb[v*65+o]-mu_s[v])*iv_s[v]*gam_s[o] + bet_s[o];
        out[(size_t)b*3968 + i] = val;
    }
}

#define SMEM_A_BYTES (11124*4)
#define SMEM_B_BYTES (18304*4)

extern "C" void kernel_launch(void* const* d_in, const int* in_sizes, int n_in,
                              void* d_out, int out_size) {
    const float* x     = (const float*)d_in[0];
    const float* U1    = (const float*)d_in[1];
    const float* U2    = (const float*)d_in[2];
    const float* U3    = (const float*)d_in[3];
    const float* be    = (const float*)d_in[4];
    const float* Ve    = (const float*)d_in[5];
    const float* W1    = (const float*)d_in[6];
    const float* W2    = (const float*)d_in[7];
    const float* W3    = (const float*)d_in[8];
    const float* bs    = (const float*)d_in[9];
    const float* Vs    = (const float*)d_in[10];
    const float* a     = (const float*)d_in[11];
    const float* Theta = (const float*)d_in[12];
    const float* tw    = (const float*)d_in[13];
    const float* tb    = (const float*)d_in[14];
    const float* rw    = (const float*)d_in[15];
    const float* rb    = (const float*)d_in[16];
    const float* gamma = (const float*)d_in[17];
    const float* beta  = (const float*)d_in[18];
    float* out = (float*)d_out;

    cudaFuncSetAttribute(stgcn_a, cudaFuncAttributeMaxDynamicSharedMemorySize, SMEM_A_BYTES);
    cudaFuncSetAttribute(stgcn_b, cudaFuncAttributeMaxDynamicSharedMemorySize, SMEM_B_BYTES);

    prep_kernel<<<48, 256>>>(tw, out);
    stgcn_a<<<NBATCH, 256, SMEM_A_BYTES>>>(x, U1, U2, U3, be, Ve, W1, W2, W3,
                                           bs, Vs, a, out);
    stgcn_b<<<NBATCH, 512, SMEM_B_BYTES>>>(x, Theta, tb, rw, rb, gamma, beta, out);
}